// round 13
// baseline (speedup 1.0000x reference)
#include <cuda_runtime.h>
#include <cuda_bf16.h>
#include <math.h>

#define N_   32
#define T_   512
#define L_   200
#define EMB_ 256
#define KEY_ 256
#define DH_  512
#define ENC_ 1024
#define VOC_ 10000
#define NBLK 148

// ---------------- static device scratch (no allocations) ----------------
__device__ float g_k   [N_*T_*KEY_];      // (N,T,KEY)
__device__ float g_v   [N_*T_*KEY_];      // (N,T,KEY)
__device__ float g_kq  [N_*T_*KEY_];      // (N,T,256)  k @ Wq^T
__device__ float g_kqT [N_*KEY_*T_];      // (N,256,T)
__device__ float g_kb  [N_*T_];           // bq . k
__device__ float g_emb [N_*L_*EMB_];      // row n*L+l
__device__ float g_q1  [N_*L_*KEY_];
__device__ float g_att [N_*L_*T_];        // energy1 -> att1 (in place)
__device__ float g_cx1 [N_*L_*KEY_];
__device__ float g_gx  [N_*L_*4*DH_];     // input-side LSTM1 gates (row n*L+l)
__device__ float g_gxT [L_*4*DH_*N_];     // (l, col, n)
__device__ float g_fco [N_*L_*EMB_];
__device__ float g_Whh1T[DH_*4*DH_];      // (512,2048)
__device__ float g_Wih2T[DH_*4*KEY_];     // (512,1024)
__device__ float g_Whh2T[KEY_*4*KEY_];    // (256,1024)
__device__ float g_b1[4*DH_];
__device__ float g_b2[4*KEY_];
__device__ float g_h1T[DH_*N_],  g_c1T[DH_*N_];     // transposed states (k-major)
__device__ float g_h2T[KEY_*N_];
__device__ float g_c2buf[2][KEY_*N_];
__device__ float g_g1T[4*DH_*N_];         // (2048,32)
__device__ float g_g2T[4*KEY_*N_];        // (1024,32)
__device__ float g_energy[N_*T_];
__device__ float g_emax[N_*4], g_esum[N_*4];
__device__ float g_P[4*N_*KEY_];          // unnormalized ctx partials (s,n,d)
__device__ float g_expe0[T_];             // exp-energies for n=0 (attns out)
__device__ unsigned g_cnt = 0, g_gen = 0;

// ---------------- helpers ----------------
__device__ __forceinline__ float sigf(float x){ return 1.f/(1.f+expf(-x)); }
__device__ __forceinline__ float warp_max(float v){
  #pragma unroll
  for (int o=16;o;o>>=1) v = fmaxf(v, __shfl_xor_sync(0xffffffffu, v, o));
  return v;
}
__device__ __forceinline__ float warp_sum(float v){
  #pragma unroll
  for (int o=16;o;o>>=1) v += __shfl_xor_sync(0xffffffffu, v, o);
  return v;
}

// software grid barrier; NBLK blocks, 1 CTA/SM (co-resident)
__device__ __forceinline__ void gridbar(){
  __syncthreads();
  __threadfence();
  if (threadIdx.x == 0){
    unsigned gen = *((volatile unsigned*)&g_gen);
    if (atomicAdd(&g_cnt, 1u) == NBLK-1u){
      g_cnt = 0u;
      __threadfence();
      atomicExch(&g_gen, gen+1u);
    } else {
      while (*((volatile unsigned*)&g_gen) == gen) { }
      __threadfence();
    }
  }
  __syncthreads();
}

// ---------------- generic tiled fp32 GEMM ----------------
// C[M,Nn] = A[M,K](lda=K) @ op(B) (+bias) (+=C if ACC), batched over z.
// BT=0: B is (K,Nn) row-major ldb.  BT=1: B is (Nn,K) row-major ldb, C=A*B^T.
template<bool BT, bool ACC>
__global__ void __launch_bounds__(256) gemm64(
    const float* __restrict__ A, const float* __restrict__ B,
    float* __restrict__ C, const float* __restrict__ bias,
    int M, int Nn, int K, int ldb, long sA, long sB, long sC)
{
  A += (long)blockIdx.z * sA; B += (long)blockIdx.z * sB; C += (long)blockIdx.z * sC;
  __shared__ float As[16][72];
  __shared__ float Bs[16][72];
  const int tid = threadIdx.x;
  const int rowBase = blockIdx.y * 64, colBase = blockIdx.x * 64;
  const int tx = tid & 15, ty = tid >> 4;
  const int ar = tid >> 2;          // 0..63
  const int ak = (tid & 3) << 2;    // 0,4,8,12
  const int bk = tid >> 4;          // 0..15
  const int bn = (tid & 15) << 2;   // 0..60
  float acc[4][4];
  #pragma unroll
  for (int i=0;i<4;i++)
    #pragma unroll
    for (int j=0;j<4;j++) acc[i][j] = 0.f;
  const int arow = rowBase + ar;

  for (int kt = 0; kt < K; kt += 16){
    float4 a4 = make_float4(0.f,0.f,0.f,0.f);
    if (arow < M) a4 = *(const float4*)(A + (long)arow*K + kt + ak);
    As[ak  ][ar] = a4.x; As[ak+1][ar] = a4.y; As[ak+2][ar] = a4.z; As[ak+3][ar] = a4.w;
    if (BT){
      float4 b4 = make_float4(0.f,0.f,0.f,0.f);
      int j = colBase + ar;
      if (j < Nn) b4 = *(const float4*)(B + (long)j*ldb + kt + ak);
      Bs[ak  ][ar] = b4.x; Bs[ak+1][ar] = b4.y; Bs[ak+2][ar] = b4.z; Bs[ak+3][ar] = b4.w;
    } else {
      float4 b4 = make_float4(0.f,0.f,0.f,0.f);
      int j = colBase + bn;
      if (j < Nn) b4 = *(const float4*)(B + (long)(kt+bk)*ldb + j);
      *(float4*)&Bs[bk][bn] = b4;
    }
    __syncthreads();
    #pragma unroll
    for (int kk=0;kk<16;kk++){
      float4 av = *(const float4*)&As[kk][ty<<2];
      float4 bv = *(const float4*)&Bs[kk][tx<<2];
      float a[4] = {av.x,av.y,av.z,av.w};
      float b[4] = {bv.x,bv.y,bv.z,bv.w};
      #pragma unroll
      for (int i=0;i<4;i++)
        #pragma unroll
        for (int j=0;j<4;j++) acc[i][j] = fmaf(a[i], b[j], acc[i][j]);
    }
    __syncthreads();
  }
  #pragma unroll
  for (int i=0;i<4;i++){
    int row = rowBase + (ty<<2) + i;
    if (row >= M) continue;
    #pragma unroll
    for (int j=0;j<4;j++){
      int col = colBase + (tx<<2) + j;
      if (col >= Nn) continue;
      float vv = acc[i][j];
      if (bias) vv += bias[col];
      long off = (long)row*Nn + col;
      if (ACC) vv += C[off];
      C[off] = vv;
    }
  }
}

// ---------------- generic transpose (R,C) -> (C,R), batched over z ----------------
__global__ void transp(const float* __restrict__ in, float* __restrict__ out,
                       int R, int C, long sIn, long sOut)
{
  in  += (long)blockIdx.z * sIn;
  out += (long)blockIdx.z * sOut;
  __shared__ float t[32][33];
  int c = blockIdx.x*32 + threadIdx.x;
  #pragma unroll
  for (int i=0;i<32;i+=8){
    int r = blockIdx.y*32 + threadIdx.y + i;
    if (r < R && c < C) t[threadIdx.y+i][threadIdx.x] = in[(long)r*C + c];
  }
  __syncthreads();
  int oc = blockIdx.y*32 + threadIdx.x;
  #pragma unroll
  for (int i=0;i<32;i+=8){
    int orow = blockIdx.x*32 + threadIdx.y + i;
    if (orow < C && oc < R) out[(long)orow*R + oc] = t[threadIdx.x][threadIdx.y+i];
  }
}

// ---------------- misc prep kernels ----------------
__global__ void bias_prep(const float* b_ih1, const float* b_hh1,
                          const float* b_ih2, const float* b_hh2){
  int i = blockIdx.x*blockDim.x + threadIdx.x;
  if (i < 4*DH_)  g_b1[i] = b_ih1[i] + b_hh1[i];
  if (i < 4*KEY_) g_b2[i] = b_ih2[i] + b_hh2[i];
}
__global__ void init_state(){
  int i = blockIdx.x*blockDim.x + threadIdx.x;
  if (i < DH_*N_){ g_h1T[i] = 0.f; g_c1T[i] = 0.f; }
  if (i < KEY_*N_){ g_h2T[i] = 0.f; g_c2buf[0][i] = 0.f; g_c2buf[1][i] = 0.f; }
}
__global__ void kb_k(const float* __restrict__ bq){
  int w = threadIdx.x >> 5, lane = threadIdx.x & 31;
  int row = blockIdx.x*8 + w;
  float a = 0.f;
  #pragma unroll
  for (int i=0;i<8;i++) a += g_k[(long)row*256 + lane + i*32] * bq[lane + i*32];
  a = warp_sum(a);
  if (lane == 0) g_kb[row] = a;
}
__global__ void embed_k(const float* __restrict__ E, const int* __restrict__ text){
  int r = blockIdx.x;                 // n*L + l
  int n = r / L_, l = r - n*L_;
  int tok = (l == 0) ? 0 : text[n*L_ + l - 1];
  g_emb[(long)r*EMB_ + threadIdx.x] = E[(long)tok*EMB_ + threadIdx.x];
}
__global__ void softmax1_k(const int* __restrict__ lens){
  __shared__ float red[8];
  int b = blockIdx.x;                 // n*L + l
  int n = b / L_;
  float* row = g_att + (long)b*T_;
  int len = lens[n];
  int t0 = threadIdx.x, t1 = threadIdx.x + 256;
  float e0 = (t0 < len) ? row[t0] : -1e9f;
  float e1 = (t1 < len) ? row[t1] : -1e9f;
  float m = warp_max(fmaxf(e0,e1));
  if ((threadIdx.x & 31) == 0) red[threadIdx.x>>5] = m;
  __syncthreads();
  m = red[0];
  #pragma unroll
  for (int i=1;i<8;i++) m = fmaxf(m, red[i]);
  __syncthreads();
  float p0 = expf(e0 - m), p1 = expf(e1 - m);
  float s = warp_sum(p0 + p1);
  if ((threadIdx.x & 31) == 0) red[threadIdx.x>>5] = s;
  __syncthreads();
  s = red[0];
  #pragma unroll
  for (int i=1;i<8;i++) s += red[i];
  float inv = 1.f / s;
  row[t0] = p0*inv; row[t1] = p1*inv;
}
// gx (n*L+l, 2048) -> gxT (l, col, n)
__global__ void gxT_k(){
  __shared__ float tile[32][33];
  int l = blockIdx.y;
  int colbase = blockIdx.x*32;
  int tx = threadIdx.x, ty = threadIdx.y;
  #pragma unroll
  for (int i=0;i<32;i+=8){
    int n = ty + i;
    tile[n][tx] = g_gx[((long)n*L_ + l)*2048 + colbase + tx];
  }
  __syncthreads();
  #pragma unroll
  for (int i=0;i<32;i+=8){
    int cl = ty + i;
    g_gxT[((long)l*2048 + colbase + cl)*32 + tx] = tile[tx][cl];
  }
}

// ---------------- persistent loop kernel ----------------
// block-level small gemm: out[(colbase+col)*32+n] (+= / =) sum_k W[k][colbase+col]*hT[k][n]
__device__ void blk_gemm16(const float* __restrict__ W, int ldw,
                           const float* __restrict__ hT, int K,
                           int colbase, float* __restrict__ outT,
                           const float* __restrict__ addM,
                           const float* __restrict__ addB,
                           bool accOut, float* sm)
{
  float* Ws = sm;           // [64*16]
  float* hs = sm + 1024;    // [64*32]
  float* ps = sm + 3072;    // [8*512]
  const int t = threadIdx.x;
  const int cg = t & 3;
  const int ng = (t >> 2) & 7;
  const int ks = t >> 5;
  float acc[4][4];
  #pragma unroll
  for (int i=0;i<4;i++)
    #pragma unroll
    for (int j=0;j<4;j++) acc[i][j] = 0.f;

  for (int kt = 0; kt < K; kt += 64){
    {
      int r = t >> 2, c4 = (t & 3) << 2;
      float4 w4 = *(const float4*)(W + (long)(kt + r)*ldw + colbase + c4);
      *(float4*)&Ws[r*16 + c4] = w4;
    }
    {
      const float4* src = (const float4*)(hT + (long)kt*32);
      float4* dst = (float4*)hs;
      dst[t] = src[t];
      dst[t+256] = src[t+256];
    }
    __syncthreads();
    #pragma unroll
    for (int kk=0;kk<8;kk++){
      int k = ks*8 + kk;
      float4 w4 = *(const float4*)&Ws[k*16 + (cg<<2)];
      float4 h4 = *(const float4*)&hs[k*32 + (ng<<2)];
      float w[4] = {w4.x,w4.y,w4.z,w4.w};
      float h[4] = {h4.x,h4.y,h4.z,h4.w};
      #pragma unroll
      for (int i=0;i<4;i++)
        #pragma unroll
        for (int j=0;j<4;j++) acc[i][j] = fmaf(w[i], h[j], acc[i][j]);
    }
    __syncthreads();
  }
  #pragma unroll
  for (int i=0;i<4;i++)
    #pragma unroll
    for (int j=0;j<4;j++)
      ps[ks*512 + ((cg<<2)+i)*32 + (ng<<2)+j] = acc[i][j];
  __syncthreads();
  #pragma unroll
  for (int i=0;i<2;i++){
    int id = t + i*256;
    float s = 0.f;
    #pragma unroll
    for (int k8=0;k8<8;k8++) s += ps[k8*512 + id];
    int col = id >> 5, n = id & 31;
    long o = (long)(colbase + col)*32 + n;
    if (addM) s += addM[o];
    if (addB) s += addB[colbase + col];
    if (accOut) s += outT[o];
    outT[o] = s;
  }
  __syncthreads();
}

__global__ void __launch_bounds__(256, 1) loop_k(
    const int* __restrict__ lens,
    const float* __restrict__ Wfc, const float* __restrict__ bfc,
    float* __restrict__ out_att)
{
  __shared__ float sm[8704];
  const int b = blockIdx.x;
  const int t = threadIdx.x;

  for (int l = 0; l < L_; l++){
    const int p = l & 1;
    // ---- S1: g1 = gxT[l] + h1 @ Whh1T  (blocks 0..127) ----
    if (b < 128)
      blk_gemm16(g_Whh1T, 2048, g_h1T, 512, b*16, g_g1T,
                 g_gxT + (long)l*2048*32, nullptr, false, sm);
    gridbar();
    // ---- S2: g2 = b2 + h2_prev @ Whh2T (0..63) ; LSTM1 update (64..127) ----
    if (b < 64){
      blk_gemm16(g_Whh2T, 1024, g_h2T, 256, b*16, g_g2T,
                 nullptr, g_b2, false, sm);
    } else if (b < 128){
      int id = (b-64)*256 + t;
      int n = id & 31, j = id >> 5;
      float gi = g_g1T[j*32+n];
      float gf = g_g1T[(512+j)*32+n];
      float gg = g_g1T[(1024+j)*32+n];
      float go = g_g1T[(1536+j)*32+n];
      float c = sigf(gf)*g_c1T[j*32+n] + sigf(gi)*tanhf(gg);
      g_c1T[j*32+n] = c;
      g_h1T[j*32+n] = sigf(go)*tanhf(c);
    }
    gridbar();
    // ---- S3: g2 += h1 @ Wih2T (blocks 0..63) ----
    if (b < 64)
      blk_gemm16(g_Wih2T, 1024, g_h1T, 512, b*16, g_g2T,
                 nullptr, nullptr, true, sm);
    gridbar();
    // ---- S4: per (n, t-tile): recompute h2/c2 locally; energy + tile max ----
    if (b < 128){
      int n = b >> 2, s = b & 3;
      float* h2s = sm;            // [256]
      float* ep  = sm + 256;      // [256]
      float* es  = sm + 512;      // [128]
      {
        int e = t;
        float gi = g_g2T[e*32+n];
        float gf = g_g2T[(256+e)*32+n];
        float gg = g_g2T[(512+e)*32+n];
        float go = g_g2T[(768+e)*32+n];
        float c = sigf(gf)*g_c2buf[p][e*32+n] + sigf(gi)*tanhf(gg);
        float h = sigf(go)*tanhf(c);
        h2s[e] = h;
        if (s == 0){ g_h2T[e*32+n] = h; g_c2buf[1-p][e*32+n] = c; }
      }
      __syncthreads();
      {
        int tl = t & 127, half = t >> 7;
        int tg = s*128 + tl;
        const float* kq = g_kqT + ((long)n*256 + half*128)*T_ + tg;
        float a = 0.f;
        #pragma unroll 4
        for (int e=0;e<128;e++) a += h2s[half*128 + e] * kq[(long)e*T_];
        ep[half*128 + tl] = a;
      }
      __syncthreads();
      if (t < 128){
        int tg = s*128 + t;
        float e = ep[t] + ep[128+t] + g_kb[n*T_ + tg];
        if (tg >= lens[n]) e = -1e9f;
        g_energy[n*T_ + tg] = e;
        es[t] = e;
      }
      __syncthreads();
      if (t < 32){
        float m = es[t];
        #pragma unroll
        for (int i=1;i<4;i++) m = fmaxf(m, es[t + i*32]);
        m = warp_max(m);
        if (t == 0) g_emax[n*4 + s] = m;
      }
    }
    gridbar();
    // ---- S5: exp + tile-sum + unnormalized ctx partials ----
    if (b < 128){
      int n = b >> 2, s = b & 3;
      float* pe = sm;   // [128]
      float m = fmaxf(fmaxf(g_emax[n*4], g_emax[n*4+1]),
                      fmaxf(g_emax[n*4+2], g_emax[n*4+3]));
      if (t < 128){
        float pp = expf(g_energy[n*T_ + s*128 + t] - m);
        pe[t] = pp;
        if (n == 0) g_expe0[s*128 + t] = pp;
      }
      __syncthreads();
      if (t < 32){
        float su = pe[t] + pe[t+32] + pe[t+64] + pe[t+96];
        su = warp_sum(su);
        if (t == 0) g_esum[n*4 + s] = su;
      }
      {
        int d = t;
        const float* vv = g_v + ((long)n*T_ + s*128)*256 + d;
        float a = 0.f;
        #pragma unroll 4
        for (int tt=0;tt<128;tt++) a += pe[tt] * vv[(long)tt*256];
        g_P[((s*32 + n)<<8) + d] = a;
      }
    }
    gridbar();
    // ---- S6: fco (blocks 0..31) + attns writer (block 32). no barrier to next S1 ----
    if (b < 32){
      float* sInv  = sm;        // [32]
      float* ctx2s = sm + 32;   // [256*33]
      if (t < 32){
        float S = g_esum[t*4] + g_esum[t*4+1] + g_esum[t*4+2] + g_esum[t*4+3];
        sInv[t] = 1.f / S;
      }
      __syncthreads();
      #pragma unroll 4
      for (int i=0;i<32;i++){
        int id = t + i*256;
        int d = id & 255, n = id >> 8;
        float a = g_P[(n<<8)+d] + g_P[((32+n)<<8)+d]
                + g_P[((64+n)<<8)+d] + g_P[((96+n)<<8)+d];
        ctx2s[d*33 + n] = a * sInv[n];
      }
      __syncthreads();
      int m = b*8 + (t >> 5), n = t & 31;
      float a = bfc[m];
      #pragma unroll 4
      for (int k2=0;k2<256;k2++) a = fmaf(g_h2T[k2*32+n], Wfc[k2*256 + m], a);
      #pragma unroll 4
      for (int d=0;d<256;d++)   a = fmaf(ctx2s[d*33+n], Wfc[(256+d)*256 + m], a);
      a = fminf(1.f, fmaxf(-1.f, a));
      g_fco[((long)n*L_ + l)*256 + m] = a;
      __syncthreads();
    } else if (b == 32){
      float S0 = g_esum[0] + g_esum[1] + g_esum[2] + g_esum[3];
      float inv = 1.f / S0;
      #pragma unroll
      for (int i=0;i<2;i++){
        int idx = t + i*256;
        out_att[(long)l*T_ + idx] = g_expe0[idx] * inv;
      }
    }
    // next S1 touches only g1T/gxT/h1T — no hazard with S6; barrier after S1 covers all.
  }
}

// ---------------- launch ----------------
extern "C" void kernel_launch(void* const* d_in, const int* in_sizes, int n_in,
                              void* d_out, int out_size) {
  const float* enc    = (const float*)d_in[0];
  const int*   text   = (const int*)  d_in[1];
  const int*   lens   = (const int*)  d_in[2];
  const float* E      = (const float*)d_in[3];
  const float* Wk     = (const float*)d_in[4];
  const float* bk     = (const float*)d_in[5];
  const float* Wv     = (const float*)d_in[6];
  const float* bv     = (const float*)d_in[7];
  const float* Wq     = (const float*)d_in[8];
  const float* bq     = (const float*)d_in[9];
  const float* W_ih1  = (const float*)d_in[10];
  const float* W_hh1  = (const float*)d_in[11];
  const float* b_ih1  = (const float*)d_in[12];
  const float* b_hh1  = (const float*)d_in[13];
  const float* W_ih2  = (const float*)d_in[14];
  const float* W_hh2  = (const float*)d_in[15];
  const float* b_ih2  = (const float*)d_in[16];
  const float* b_hh2  = (const float*)d_in[17];
  const float* Wfc    = (const float*)d_in[18];
  const float* bfc    = (const float*)d_in[19];
  const float* b_char = (const float*)d_in[20];
  float* out = (float*)d_out;

  float *pWhh1T, *pWih2T, *pWhh2T, *pK, *pV, *pKq, *pKqT, *pEmb, *pQ1, *pAtt, *pCx1, *pGx, *pFco;
  cudaGetSymbolAddress((void**)&pWhh1T, g_Whh1T);
  cudaGetSymbolAddress((void**)&pWih2T, g_Wih2T);
  cudaGetSymbolAddress((void**)&pWhh2T, g_Whh2T);
  cudaGetSymbolAddress((void**)&pK,   g_k);
  cudaGetSymbolAddress((void**)&pV,   g_v);
  cudaGetSymbolAddress((void**)&pKq,  g_kq);
  cudaGetSymbolAddress((void**)&pKqT, g_kqT);
  cudaGetSymbolAddress((void**)&pEmb, g_emb);
  cudaGetSymbolAddress((void**)&pQ1,  g_q1);
  cudaGetSymbolAddress((void**)&pAtt, g_att);
  cudaGetSymbolAddress((void**)&pCx1, g_cx1);
  cudaGetSymbolAddress((void**)&pGx,  g_gx);
  cudaGetSymbolAddress((void**)&pFco, g_fco);
  float* pB1; cudaGetSymbolAddress((void**)&pB1, g_b1);

  // weight prep
  bias_prep<<<8, 256>>>(b_ih1, b_hh1, b_ih2, b_hh2);
  init_state<<<64, 256>>>();
  transp<<<dim3(16,64,1), dim3(32,8)>>>(W_hh1, pWhh1T, 2048, 512, 0, 0);
  transp<<<dim3(16,32,1), dim3(32,8)>>>(W_ih2, pWih2T, 1024, 512, 0, 0);
  transp<<<dim3(8,32,1),  dim3(32,8)>>>(W_hh2, pWhh2T, 1024, 256, 0, 0);

  // k, v projections: (16384,1024) @ (1024,256)
  gemm64<false,false><<<dim3(4,256,1), 256>>>(enc, Wk, pK, bk, N_*T_, KEY_, ENC_, KEY_, 0,0,0);
  gemm64<false,false><<<dim3(4,256,1), 256>>>(enc, Wv, pV, bv, N_*T_, KEY_, ENC_, KEY_, 0,0,0);
  // kq = k @ Wq^T ; kb = k . bq
  gemm64<true,false><<<dim3(4,256,1), 256>>>(pK, Wq, pKq, nullptr, N_*T_, 256, KEY_, KEY_, 0,0,0);
  kb_k<<<N_*T_/8, 256>>>(bq);
  transp<<<dim3(8,16,N_), dim3(32,8)>>>(pKq, pKqT, T_, 256, (long)T_*256, (long)256*T_);

  // embeddings, q1, attend(q1), ctx1
  embed_k<<<N_*L_, 256>>>(E, text);
  gemm64<false,false><<<dim3(4,100,1), 256>>>(pEmb, Wq, pQ1, bq, N_*L_, KEY_, EMB_, KEY_, 0,0,0);
  gemm64<true,false><<<dim3(8,4,N_), 256>>>(pQ1, pK, pAtt, nullptr, L_, T_, KEY_, KEY_,
                                            (long)L_*KEY_, (long)T_*KEY_, (long)L_*T_);
  softmax1_k<<<N_*L_, 256>>>(lens);
  gemm64<false,false><<<dim3(4,4,N_), 256>>>(pAtt, pV, pCx1, nullptr, L_, KEY_, T_, KEY_,
                                             (long)L_*T_, (long)T_*KEY_, (long)L_*KEY_);
  // gx = emb @ W_ih1[:, :256]^T + ctx1 @ W_ih1[:, 256:]^T + (b_ih1+b_hh1)
  gemm64<true,false><<<dim3(32,100,1), 256>>>(pEmb, W_ih1, pGx, pB1, N_*L_, 4*DH_, EMB_, EMB_+KEY_, 0,0,0);
  gemm64<true,true ><<<dim3(32,100,1), 256>>>(pCx1, W_ih1 + EMB_, pGx, nullptr, N_*L_, 4*DH_, KEY_, EMB_+KEY_, 0,0,0);
  gxT_k<<<dim3(64, L_), dim3(32,8)>>>();

  // sequential decoder loop (persistent, grid-barriered)
  loop_k<<<NBLK, 256>>>(lens, Wfc, bfc, out + (long)N_*L_*VOC_);

  // preds = fco @ E^T + b_char  -> (N,L,VOCAB)
  gemm64<true,false><<<dim3(157,100,1), 256>>>(pFco, E, out, b_char, N_*L_, VOC_, EMB_, EMB_, 0,0,0);
}

// round 15
// speedup vs baseline: 1.0379x; 1.0379x over previous
#include <cuda_runtime.h>
#include <cuda_bf16.h>
#include <math.h>

#define N_   32
#define T_   512
#define L_   200
#define EMB_ 256
#define KEY_ 256
#define DH_  512
#define ENC_ 1024
#define VOC_ 10000
#define NBLK 148
#define IN1LD 512   // row stride of fused [emb|ctx1] buffer

// ---------------- static device scratch (no allocations) ----------------
__device__ float g_k   [N_*T_*KEY_];      // (N,T,KEY)
__device__ float g_v   [N_*T_*KEY_];      // (N,T,KEY)
__device__ float g_kq  [N_*T_*KEY_];      // (N,T,256)  k @ Wq^T
__device__ float g_kqT [N_*KEY_*T_];      // (N,256,T)
__device__ float g_kb  [N_*T_];           // bq . k
__device__ float g_in1 [N_*L_*IN1LD];     // fused [emb | ctx1], ld=512, row n*L+l
__device__ float g_q1  [N_*L_*KEY_];
__device__ float g_att [N_*L_*T_];        // energy1 -> att1 (in place)
__device__ float g_gx  [N_*L_*4*DH_];     // input-side LSTM1 gates (row n*L+l)
__device__ float g_gxT [L_*4*DH_*N_];     // (l, col, n)
__device__ float g_fco [N_*L_*EMB_];
__device__ float g_Whh1T[DH_*4*DH_];      // (512,2048)
__device__ float g_Wih2T[DH_*4*KEY_];     // (512,1024)
__device__ float g_Whh2T[KEY_*4*KEY_];    // (256,1024)
__device__ float g_b1[4*DH_];
__device__ float g_b2[4*KEY_];
__device__ float g_h1T[DH_*N_],  g_c1T[DH_*N_];     // transposed states (k-major)
__device__ float g_h2T[KEY_*N_];
__device__ float g_c2buf[2][KEY_*N_];
__device__ float g_g1T[4*DH_*N_];         // (2048,32)
__device__ float g_g2T[4*KEY_*N_];        // (1024,32)
__device__ float g_emax[N_*4], g_esum[N_*4];
__device__ float g_P[4*N_*KEY_];          // tile-scaled ctx partials (s,n,d)
__device__ float g_expe0[T_];             // tile-scaled exp-energies for n=0
__device__ unsigned g_cnt = 0, g_gen = 0;

// ---------------- helpers ----------------
__device__ __forceinline__ float sigf(float x){ return 1.f/(1.f+expf(-x)); }
__device__ __forceinline__ float warp_max(float v){
  #pragma unroll
  for (int o=16;o;o>>=1) v = fmaxf(v, __shfl_xor_sync(0xffffffffu, v, o));
  return v;
}
__device__ __forceinline__ float warp_sum(float v){
  #pragma unroll
  for (int o=16;o;o>>=1) v += __shfl_xor_sync(0xffffffffu, v, o);
  return v;
}

// software grid barrier; NBLK blocks, 1 CTA/SM (co-resident)
__device__ __forceinline__ void gridbar(){
  __syncthreads();
  __threadfence();
  if (threadIdx.x == 0){
    unsigned gen = *((volatile unsigned*)&g_gen);
    if (atomicAdd(&g_cnt, 1u) == NBLK-1u){
      g_cnt = 0u;
      __threadfence();
      atomicExch(&g_gen, gen+1u);
    } else {
      while (*((volatile unsigned*)&g_gen) == gen) { }
      __threadfence();
    }
  }
  __syncthreads();
}

// ---------------- 128x128 fp32 GEMM, 8x8 microtile, double-buffered ----------------
// C[M,Nn] = A[M,K](lda) @ op(B) (+bias) (+=C if ACC), batched over z.
// BT=0: B is (K,Nn) row-major ldb.  BT=1: B is (Nn,K) row-major ldb, C=A*B^T.
// Requires: K % 8 == 0, Nn % 4 == 0, all pointers 16B aligned, lda/ldb/ldc % 4 == 0.
template<bool BT, bool ACC>
__global__ void __launch_bounds__(256) gemm128(
    const float* __restrict__ A, const float* __restrict__ B,
    float* __restrict__ C, const float* __restrict__ bias,
    int M, int Nn, int K, int lda, int ldb, int ldc,
    long sA, long sB, long sC)
{
  A += (long)blockIdx.z * sA; B += (long)blockIdx.z * sB; C += (long)blockIdx.z * sC;
  __shared__ float As[2][8][128];
  __shared__ float Bs[2][8][128];
  const int tid = threadIdx.x;
  const int rBase = blockIdx.y * 128, cBase = blockIdx.x * 128;
  const int tr = tid >> 4, tc = tid & 15;        // 16x16 thread grid, 8x8 each
  const int ar = tid >> 1, akq = (tid & 1) * 4;  // A loader: row ar, k akq..akq+3
  const int garow = rBase + ar;
  const int bk = tid >> 5, bc = (tid & 31) * 4;  // B loader (BT=0)
  const int gbcol0 = cBase + bc;
  const int gbrow1 = cBase + ar;                 // B loader (BT=1)

  float acc[8][8];
  #pragma unroll
  for (int i=0;i<8;i++)
    #pragma unroll
    for (int j=0;j<8;j++) acc[i][j] = 0.f;

  const int nk = K >> 3;
  float4 pa = make_float4(0.f,0.f,0.f,0.f);
  float4 pb = make_float4(0.f,0.f,0.f,0.f);
  if (garow < M) pa = *(const float4*)(A + (long)garow*lda + akq);
  if (BT){ if (gbrow1 < Nn) pb = *(const float4*)(B + (long)gbrow1*ldb + akq); }
  else   { if (gbcol0 < Nn) pb = *(const float4*)(B + (long)bk*ldb + gbcol0); }
  As[0][akq  ][ar]=pa.x; As[0][akq+1][ar]=pa.y; As[0][akq+2][ar]=pa.z; As[0][akq+3][ar]=pa.w;
  if (BT){ Bs[0][akq][ar]=pb.x; Bs[0][akq+1][ar]=pb.y; Bs[0][akq+2][ar]=pb.z; Bs[0][akq+3][ar]=pb.w; }
  else   { *(float4*)&Bs[0][bk][bc] = pb; }
  __syncthreads();

  for (int kt=0; kt<nk; kt++){
    const int cur = kt & 1;
    if (kt+1 < nk){
      const int ko = (kt+1) << 3;
      pa = make_float4(0.f,0.f,0.f,0.f);
      pb = make_float4(0.f,0.f,0.f,0.f);
      if (garow < M) pa = *(const float4*)(A + (long)garow*lda + ko + akq);
      if (BT){ if (gbrow1 < Nn) pb = *(const float4*)(B + (long)gbrow1*ldb + ko + akq); }
      else   { if (gbcol0 < Nn) pb = *(const float4*)(B + (long)(ko+bk)*ldb + gbcol0); }
    }
    #pragma unroll
    for (int kk=0;kk<8;kk++){
      float4 a0 = *(const float4*)&As[cur][kk][tr*8];
      float4 a1 = *(const float4*)&As[cur][kk][tr*8+4];
      float4 b0 = *(const float4*)&Bs[cur][kk][tc*8];
      float4 b1 = *(const float4*)&Bs[cur][kk][tc*8+4];
      float av[8] = {a0.x,a0.y,a0.z,a0.w,a1.x,a1.y,a1.z,a1.w};
      float bv[8] = {b0.x,b0.y,b0.z,b0.w,b1.x,b1.y,b1.z,b1.w};
      #pragma unroll
      for (int i=0;i<8;i++)
        #pragma unroll
        for (int j=0;j<8;j++) acc[i][j] = fmaf(av[i], bv[j], acc[i][j]);
    }
    if (kt+1 < nk){
      const int nx = (kt+1) & 1;
      As[nx][akq  ][ar]=pa.x; As[nx][akq+1][ar]=pa.y; As[nx][akq+2][ar]=pa.z; As[nx][akq+3][ar]=pa.w;
      if (BT){ Bs[nx][akq][ar]=pb.x; Bs[nx][akq+1][ar]=pb.y; Bs[nx][akq+2][ar]=pb.z; Bs[nx][akq+3][ar]=pb.w; }
      else   { *(float4*)&Bs[nx][bk][bc] = pb; }
    }
    __syncthreads();
  }

  #pragma unroll
  for (int i=0;i<8;i++){
    int row = rBase + tr*8 + i;
    if (row >= M) continue;
    #pragma unroll
    for (int j=0;j<8;j+=4){
      int col = cBase + tc*8 + j;
      if (col >= Nn) continue;   // Nn%4==0 and col%4==0 -> col+3 < Nn
      float4 vv;
      vv.x = acc[i][j]; vv.y = acc[i][j+1]; vv.z = acc[i][j+2]; vv.w = acc[i][j+3];
      if (bias){ vv.x += bias[col]; vv.y += bias[col+1]; vv.z += bias[col+2]; vv.w += bias[col+3]; }
      float* cp = C + (long)row*ldc + col;
      if (ACC){ float4 o = *(const float4*)cp; vv.x+=o.x; vv.y+=o.y; vv.z+=o.z; vv.w+=o.w; }
      *(float4*)cp = vv;
    }
  }
}

// ---------------- generic transpose (R,C) -> (C,R), batched over z ----------------
__global__ void transp(const float* __restrict__ in, float* __restrict__ out,
                       int R, int C, long sIn, long sOut)
{
  in  += (long)blockIdx.z * sIn;
  out += (long)blockIdx.z * sOut;
  __shared__ float t[32][33];
  int c = blockIdx.x*32 + threadIdx.x;
  #pragma unroll
  for (int i=0;i<32;i+=8){
    int r = blockIdx.y*32 + threadIdx.y + i;
    if (r < R && c < C) t[threadIdx.y+i][threadIdx.x] = in[(long)r*C + c];
  }
  __syncthreads();
  int oc = blockIdx.y*32 + threadIdx.x;
  #pragma unroll
  for (int i=0;i<32;i+=8){
    int orow = blockIdx.x*32 + threadIdx.y + i;
    if (orow < C && oc < R) out[(long)orow*R + oc] = t[threadIdx.x][threadIdx.y+i];
  }
}

// ---------------- misc prep kernels ----------------
__global__ void bias_prep(const float* b_ih1, const float* b_hh1,
                          const float* b_ih2, const float* b_hh2){
  int i = blockIdx.x*blockDim.x + threadIdx.x;
  if (i < 4*DH_)  g_b1[i] = b_ih1[i] + b_hh1[i];
  if (i < 4*KEY_) g_b2[i] = b_ih2[i] + b_hh2[i];
}
__global__ void init_state(){
  int i = blockIdx.x*blockDim.x + threadIdx.x;
  if (i < DH_*N_){ g_h1T[i] = 0.f; g_c1T[i] = 0.f; }
  if (i < KEY_*N_){ g_h2T[i] = 0.f; g_c2buf[0][i] = 0.f; g_c2buf[1][i] = 0.f; }
}
__global__ void kb_k(const float* __restrict__ bq){
  int w = threadIdx.x >> 5, lane = threadIdx.x & 31;
  int row = blockIdx.x*8 + w;
  float a = 0.f;
  #pragma unroll
  for (int i=0;i<8;i++) a += g_k[(long)row*256 + lane + i*32] * bq[lane + i*32];
  a = warp_sum(a);
  if (lane == 0) g_kb[row] = a;
}
__global__ void embed_k(const float* __restrict__ E, const int* __restrict__ text){
  int r = blockIdx.x;                 // n*L + l
  int n = r / L_, l = r - n*L_;
  int tok = (l == 0) ? 0 : text[n*L_ + l - 1];
  g_in1[(long)r*IN1LD + threadIdx.x] = E[(long)tok*EMB_ + threadIdx.x];
}
__global__ void softmax1_k(const int* __restrict__ lens){
  __shared__ float red[8];
  int b = blockIdx.x;                 // n*L + l
  int n = b / L_;
  float* row = g_att + (long)b*T_;
  int len = lens[n];
  int t0 = threadIdx.x, t1 = threadIdx.x + 256;
  float e0 = (t0 < len) ? row[t0] : -1e30f;
  float e1 = (t1 < len) ? row[t1] : -1e30f;
  float m = warp_max(fmaxf(e0,e1));
  if ((threadIdx.x & 31) == 0) red[threadIdx.x>>5] = m;
  __syncthreads();
  m = red[0];
  #pragma unroll
  for (int i=1;i<8;i++) m = fmaxf(m, red[i]);
  __syncthreads();
  float p0 = (t0 < len) ? expf(e0 - m) : 0.f;
  float p1 = (t1 < len) ? expf(e1 - m) : 0.f;
  float s = warp_sum(p0 + p1);
  if ((threadIdx.x & 31) == 0) red[threadIdx.x>>5] = s;
  __syncthreads();
  s = red[0];
  #pragma unroll
  for (int i=1;i<8;i++) s += red[i];
  float inv = 1.f / s;
  row[t0] = p0*inv; row[t1] = p1*inv;
}
// gx (n*L+l, 2048) -> gxT (l, col, n)
__global__ void gxT_k(){
  __shared__ float tile[32][33];
  int l = blockIdx.y;
  int colbase = blockIdx.x*32;
  int tx = threadIdx.x, ty = threadIdx.y;
  #pragma unroll
  for (int i=0;i<32;i+=8){
    int n = ty + i;
    tile[n][tx] = g_gx[((long)n*L_ + l)*2048 + colbase + tx];
  }
  __syncthreads();
  #pragma unroll
  for (int i=0;i<32;i+=8){
    int cl = ty + i;
    g_gxT[((long)l*2048 + colbase + cl)*32 + tx] = tile[tx][cl];
  }
}

// ---------------- persistent loop kernel ----------------
// block-level small gemm: out[(colbase+col)*32+n] (+= / =) sum_k W[k][colbase+col]*hT[k][n]
__device__ void blk_gemm16(const float* __restrict__ W, int ldw,
                           const float* __restrict__ hT, int K,
                           int colbase, float* __restrict__ outT,
                           const float* __restrict__ addM,
                           const float* __restrict__ addB,
                           bool accOut, float* sm)
{
  float* Ws = sm;           // [64*16]
  float* hs = sm + 1024;    // [64*32]
  float* ps = sm + 3072;    // [8*512]
  const int t = threadIdx.x;
  const int cg = t & 3;
  const int ng = (t >> 2) & 7;
  const int ks = t >> 5;
  float acc[4][4];
  #pragma unroll
  for (int i=0;i<4;i++)
    #pragma unroll
    for (int j=0;j<4;j++) acc[i][j] = 0.f;

  for (int kt = 0; kt < K; kt += 64){
    {
      int r = t >> 2, c4 = (t & 3) << 2;
      float4 w4 = *(const float4*)(W + (long)(kt + r)*ldw + colbase + c4);
      *(float4*)&Ws[r*16 + c4] = w4;
    }
    {
      const float4* src = (const float4*)(hT + (long)kt*32);
      float4* dst = (float4*)hs;
      dst[t] = src[t];
      dst[t+256] = src[t+256];
    }
    __syncthreads();
    #pragma unroll
    for (int kk=0;kk<8;kk++){
      int k = ks*8 + kk;
      float4 w4 = *(const float4*)&Ws[k*16 + (cg<<2)];
      float4 h4 = *(const float4*)&hs[k*32 + (ng<<2)];
      float w[4] = {w4.x,w4.y,w4.z,w4.w};
      float h[4] = {h4.x,h4.y,h4.z,h4.w};
      #pragma unroll
      for (int i=0;i<4;i++)
        #pragma unroll
        for (int j=0;j<4;j++) acc[i][j] = fmaf(w[i], h[j], acc[i][j]);
    }
    __syncthreads();
  }
  #pragma unroll
  for (int i=0;i<4;i++)
    #pragma unroll
    for (int j=0;j<4;j++)
      ps[ks*512 + ((cg<<2)+i)*32 + (ng<<2)+j] = acc[i][j];
  __syncthreads();
  #pragma unroll
  for (int i=0;i<2;i++){
    int id = t + i*256;
    float s = 0.f;
    #pragma unroll
    for (int k8=0;k8<8;k8++) s += ps[k8*512 + id];
    int col = id >> 5, n = id & 31;
    long o = (long)(colbase + col)*32 + n;
    if (addM) s += addM[o];
    if (addB) s += addB[colbase + col];
    if (accOut) s += outT[o];
    outT[o] = s;
  }
  __syncthreads();
}

__global__ void __launch_bounds__(256, 1) loop_k(
    const int* __restrict__ lens,
    const float* __restrict__ Wfc, const float* __restrict__ bfc,
    float* __restrict__ out_att)
{
  __shared__ float sm[8704];
  const int b = blockIdx.x;
  const int t = threadIdx.x;

  for (int l = 0; l < L_; l++){
    const int p = l & 1;
    // ---- S1: g1 = gxT[l] + h1 @ Whh1T  (blocks 0..127) ----
    if (b < 128)
      blk_gemm16(g_Whh1T, 2048, g_h1T, 512, b*16, g_g1T,
                 g_gxT + (long)l*2048*32, nullptr, false, sm);
    gridbar();
    // ---- S2: g2 = b2 + h2_prev @ Whh2T (0..63) ; LSTM1 update (64..127) ----
    if (b < 64){
      blk_gemm16(g_Whh2T, 1024, g_h2T, 256, b*16, g_g2T,
                 nullptr, g_b2, false, sm);
    } else if (b < 128){
      int id = (b-64)*256 + t;
      int n = id & 31, j = id >> 5;
      float gi = g_g1T[j*32+n];
      float gf = g_g1T[(512+j)*32+n];
      float gg = g_g1T[(1024+j)*32+n];
      float go = g_g1T[(1536+j)*32+n];
      float c = sigf(gf)*g_c1T[j*32+n] + sigf(gi)*tanhf(gg);
      g_c1T[j*32+n] = c;
      g_h1T[j*32+n] = sigf(go)*tanhf(c);
    }
    gridbar();
    // ---- S3: g2 += h1 @ Wih2T (blocks 0..63) ----
    if (b < 64)
      blk_gemm16(g_Wih2T, 1024, g_h1T, 512, b*16, g_g2T,
                 nullptr, nullptr, true, sm);
    gridbar();
    // ---- S45: per (n, t-tile): h2/c2 recompute; energy; tile-local softmax pieces ----
    if (b < 128){
      int n = b >> 2, s = b & 3;
      float* h2s = sm;            // [256]
      float* ep  = sm + 256;      // [256]
      float* pe  = sm + 512;      // [128]
      float* red = sm + 648;      // [1]
      {
        int e = t;
        float gi = g_g2T[e*32+n];
        float gf = g_g2T[(256+e)*32+n];
        float gg = g_g2T[(512+e)*32+n];
        float go = g_g2T[(768+e)*32+n];
        float c = sigf(gf)*g_c2buf[p][e*32+n] + sigf(gi)*tanhf(gg);
        float h = sigf(go)*tanhf(c);
        h2s[e] = h;
        if (s == 0){ g_h2T[e*32+n] = h; g_c2buf[1-p][e*32+n] = c; }
      }
      __syncthreads();
      {
        int tl = t & 127, half = t >> 7;
        int tg = s*128 + tl;
        const float* kq = g_kqT + ((long)n*256 + half*128)*T_ + tg;
        float a = 0.f;
        #pragma unroll 4
        for (int e=0;e<128;e++) a += h2s[half*128 + e] * kq[(long)e*T_];
        ep[half*128 + tl] = a;
      }
      __syncthreads();
      float eng = -1e30f; bool valid = false;
      if (t < 128){
        int tg = s*128 + t;
        eng = ep[t] + ep[128+t] + g_kb[n*T_ + tg];
        valid = (tg < lens[n]);
        if (!valid) eng = -1e30f;
        pe[t] = eng;
      }
      __syncthreads();
      if (t < 32){
        float m = fmaxf(fmaxf(pe[t],pe[t+32]), fmaxf(pe[t+64],pe[t+96]));
        m = warp_max(m);
        if (t == 0){ red[0] = m; g_emax[n*4 + s] = m; }
      }
      __syncthreads();
      float m_s = red[0];
      if (t < 128){
        float pv = valid ? expf(eng - m_s) : 0.f;
        pe[t] = pv;
        if (n == 0) g_expe0[s*128 + t] = pv;
      }
      __syncthreads();
      if (t < 32){
        float su = pe[t] + pe[t+32] + pe[t+64] + pe[t+96];
        su = warp_sum(su);
        if (t == 0) g_esum[n*4 + s] = su;
      }
      {
        int d = t;
        const float* vv = g_v + ((long)n*T_ + s*128)*256 + d;
        float a = 0.f;
        #pragma unroll 4
        for (int tt=0;tt<128;tt++) a = fmaf(pe[tt], vv[(long)tt*256], a);
        g_P[((s*32 + n)<<8) + d] = a;
      }
    }
    gridbar();
    // ---- S6: combine tiles + fco (blocks 0..31), attn writer (block 32); no barrier to S1 ----
    if (b < 32){
      float* sw    = sm;        // [128] = per-(n,s) weight/D
      float* ctx2s = sm + 128;  // [256*33]
      if (t < 32){
        float m0=g_emax[t*4], m1=g_emax[t*4+1], m2=g_emax[t*4+2], m3=g_emax[t*4+3];
        float M = fmaxf(fmaxf(m0,m1), fmaxf(m2,m3));
        float w0=expf(m0-M), w1=expf(m1-M), w2=expf(m2-M), w3=expf(m3-M);
        float D = g_esum[t*4]*w0 + g_esum[t*4+1]*w1 + g_esum[t*4+2]*w2 + g_esum[t*4+3]*w3;
        float inv = 1.f / D;
        sw[t*4]=w0*inv; sw[t*4+1]=w1*inv; sw[t*4+2]=w2*inv; sw[t*4+3]=w3*inv;
      }
      __syncthreads();
      #pragma unroll 4
      for (int i=0;i<32;i++){
        int id = t + i*256;
        int d = id & 255, n = id >> 8;
        float a = g_P[(n<<8)+d]*sw[n*4]   + g_P[((32+n)<<8)+d]*sw[n*4+1]
                + g_P[((64+n)<<8)+d]*sw[n*4+2] + g_P[((96+n)<<8)+d]*sw[n*4+3];
        ctx2s[d*33 + n] = a;
      }
      __syncthreads();
      int m = b*8 + (t >> 5), n = t & 31;
      float a = bfc[m];
      #pragma unroll 4
      for (int k2=0;k2<256;k2++) a = fmaf(g_h2T[k2*32+n], Wfc[k2*256 + m], a);
      #pragma unroll 4
      for (int d=0;d<256;d++)   a = fmaf(ctx2s[d*33+n], Wfc[(256+d)*256 + m], a);
      a = fminf(1.f, fmaxf(-1.f, a));
      g_fco[((long)n*L_ + l)*256 + m] = a;
      __syncthreads();
    } else if (b == 32){
      float* sw = sm;   // [4]
      if (t < 4){
        float m0=g_emax[0], m1=g_emax[1], m2=g_emax[2], m3=g_emax[3];
        float M = fmaxf(fmaxf(m0,m1), fmaxf(m2,m3));
        float ms = (t==0)?m0:(t==1)?m1:(t==2)?m2:m3;
        float w0=expf(m0-M), w1=expf(m1-M), w2=expf(m2-M), w3=expf(m3-M);
        float D = g_esum[0]*w0 + g_esum[1]*w1 + g_esum[2]*w2 + g_esum[3]*w3;
        sw[t] = expf(ms - M) / D;
      }
      __syncthreads();
      #pragma unroll
      for (int i=0;i<2;i++){
        int idx = t + i*256;
        out_att[(long)l*T_ + idx] = g_expe0[idx] * sw[idx >> 7];
      }
      __syncthreads();
    }
  }
}

// ---------------- launch ----------------
extern "C" void kernel_launch(void* const* d_in, const int* in_sizes, int n_in,
                              void* d_out, int out_size) {
  const float* enc    = (const float*)d_in[0];
  const int*   text   = (const int*)  d_in[1];
  const int*   lens   = (const int*)  d_in[2];
  const float* E      = (const float*)d_in[3];
  const float* Wk     = (const float*)d_in[4];
  const float* bk     = (const float*)d_in[5];
  const float* Wv     = (const float*)d_in[6];
  const float* bv     = (const float*)d_in[7];
  const float* Wq     = (const float*)d_in[8];
  const float* bq     = (const float*)d_in[9];
  const float* W_ih1  = (const float*)d_in[10];
  const float* W_hh1  = (const float*)d_in[11];
  const float* b_ih1  = (const float*)d_in[12];
  const float* b_hh1  = (const float*)d_in[13];
  const float* W_ih2  = (const float*)d_in[14];
  const float* W_hh2  = (const float*)d_in[15];
  const float* b_ih2  = (const float*)d_in[16];
  const float* b_hh2  = (const float*)d_in[17];
  const float* Wfc    = (const float*)d_in[18];
  const float* bfc    = (const float*)d_in[19];
  const float* b_char = (const float*)d_in[20];
  float* out = (float*)d_out;

  float *pWhh1T, *pWih2T, *pWhh2T, *pK, *pV, *pKq, *pKqT, *pIn1, *pQ1, *pAtt, *pGx, *pFco, *pB1;
  cudaGetSymbolAddress((void**)&pWhh1T, g_Whh1T);
  cudaGetSymbolAddress((void**)&pWih2T, g_Wih2T);
  cudaGetSymbolAddress((void**)&pWhh2T, g_Whh2T);
  cudaGetSymbolAddress((void**)&pK,   g_k);
  cudaGetSymbolAddress((void**)&pV,   g_v);
  cudaGetSymbolAddress((void**)&pKq,  g_kq);
  cudaGetSymbolAddress((void**)&pKqT, g_kqT);
  cudaGetSymbolAddress((void**)&pIn1, g_in1);
  cudaGetSymbolAddress((void**)&pQ1,  g_q1);
  cudaGetSymbolAddress((void**)&pAtt, g_att);
  cudaGetSymbolAddress((void**)&pGx,  g_gx);
  cudaGetSymbolAddress((void**)&pFco, g_fco);
  cudaGetSymbolAddress((void**)&pB1,  g_b1);

  // 1-3: prep (keep count low so profiled slots 4-6 land on gemm128)
  bias_prep<<<8, 256>>>(b_ih1, b_hh1, b_ih2, b_hh2);
  init_state<<<64, 256>>>();
  embed_k<<<N_*L_, 256>>>(E, text);

  // 4-6: big projections (also the ncu-profiled slots)
  gemm128<false,false><<<dim3(2,128,1), 256>>>(enc, Wk, pK, bk,
      N_*T_, KEY_, ENC_, ENC_, KEY_, KEY_, 0,0,0);
  gemm128<false,false><<<dim3(2,128,1), 256>>>(enc, Wv, pV, bv,
      N_*T_, KEY_, ENC_, ENC_, KEY_, KEY_, 0,0,0);
  gemm128<true,false><<<dim3(2,128,1), 256>>>(pK, Wq, pKq, nullptr,
      N_*T_, 256, KEY_, KEY_, KEY_, 256, 0,0,0);

  kb_k<<<N_*T_/8, 256>>>(bq);
  transp<<<dim3(16,64,1), dim3(32,8)>>>(W_hh1, pWhh1T, 2048, 512, 0, 0);
  transp<<<dim3(16,32,1), dim3(32,8)>>>(W_ih2, pWih2T, 1024, 512, 0, 0);
  transp<<<dim3(8,32,1),  dim3(32,8)>>>(W_hh2, pWhh2T, 1024, 256, 0, 0);
  transp<<<dim3(8,16,N_), dim3(32,8)>>>(pKq, pKqT, T_, 256, (long)T_*256, (long)256*T_);

  // q1 = emb @ Wq + bq   (emb = cols 0..255 of g_in1, lda=IN1LD)
  gemm128<false,false><<<dim3(2,50,1), 256>>>(pIn1, Wq, pQ1, bq,
      N_*L_, KEY_, EMB_, IN1LD, KEY_, KEY_, 0,0,0);
  // energy1 = q1 @ k^T per batch
  gemm128<true,false><<<dim3(4,2,N_), 256>>>(pQ1, pK, pAtt, nullptr,
      L_, T_, KEY_, KEY_, KEY_, T_, (long)L_*KEY_, (long)T_*KEY_, (long)L_*T_);
  softmax1_k<<<N_*L_, 256>>>(lens);
  // ctx1 = att @ v  -> cols 256..511 of g_in1
  gemm128<false,false><<<dim3(2,2,N_), 256>>>(pAtt, pV, pIn1 + 256, nullptr,
      L_, KEY_, T_, T_, KEY_, IN1LD, (long)L_*T_, (long)T_*KEY_, (long)L_*IN1LD);
  // gx = [emb|ctx1] @ W_ih1^T + (b_ih1+b_hh1)   (single K=512 pass)
  gemm128<true,false><<<dim3(16,50,1), 256>>>(pIn1, W_ih1, pGx, pB1,
      N_*L_, 4*DH_, EMB_+KEY_, IN1LD, EMB_+KEY_, 4*DH_, 0,0,0);
  gxT_k<<<dim3(64, L_), dim3(32,8)>>>();

  // sequential decoder loop (persistent, grid-barriered)
  loop_k<<<NBLK, 256>>>(lens, Wfc, bfc, out + (long)N_*L_*VOC_);

  // preds = fco @ E^T + b_char  -> (N,L,VOCAB)
  gemm128<true,false><<<dim3(79,50,1), 256>>>(pFco, E, out, b_char,
      N_*L_, VOC_, EMB_, EMB_, EMB_, VOC_, 0,0,0);
}

// round 16
// speedup vs baseline: 1.8644x; 1.7965x over previous
#include <cuda_runtime.h>
#include <cuda_bf16.h>
#include <math.h>

#define N_   32
#define T_   512
#define L_   200
#define EMB_ 256
#define KEY_ 256
#define DH_  512
#define ENC_ 1024
#define VOC_ 10000
#define NBLK 148
#define IN1LD 512   // row stride of fused [emb|ctx1] buffer

// ---------------- static device scratch (no allocations) ----------------
__device__ float g_k   [N_*T_*KEY_];      // (N,T,KEY)
__device__ float g_v   [N_*T_*KEY_];      // (N,T,KEY)
__device__ float g_kq  [N_*T_*KEY_];      // (N,T,256)  k @ Wq^T
__device__ float g_kqT [N_*KEY_*T_];      // (N,256,T)
__device__ float g_kb  [N_*T_];           // bq . k
__device__ float g_in1 [N_*L_*IN1LD];     // fused [emb | ctx1], ld=512, row n*L+l
__device__ float g_q1  [N_*L_*KEY_];
__device__ float g_att [N_*L_*T_];        // energy1 -> att1 (in place)
__device__ float g_gx  [N_*L_*4*DH_];     // input-side LSTM1 gates (row n*L+l)
__device__ float g_gxT [L_*4*DH_*N_];     // (l, col, n)
__device__ float g_fco [N_*L_*EMB_];
__device__ float g_Whh1T[DH_*4*DH_];      // (512,2048)
__device__ float g_Wih2T[DH_*4*KEY_];     // (512,1024)
__device__ float g_Whh2T[KEY_*4*KEY_];    // (256,1024)
__device__ float g_b1[4*DH_];
__device__ float g_b2[4*KEY_];
__device__ float g_h1T[DH_*N_],  g_c1T[DH_*N_];     // transposed states (k-major)
__device__ float g_hc2T[512*N_];          // rows 0..255 = h2, rows 256..511 = ctx2
__device__ float g_c2buf[2][KEY_*N_];
__device__ float g_g1T[4*DH_*N_];         // (2048,32)
__device__ float g_g2T[4*KEY_*N_];        // (1024,32)
__device__ float g_emax[N_*4], g_esum[N_*4];
__device__ float g_P[4*N_*KEY_];          // tile-scaled ctx partials (s,n,d)
__device__ float g_expe0[T_];             // tile-scaled exp-energies for n=0
__device__ unsigned g_cnt = 0, g_gen = 0;

// ---------------- helpers ----------------
__device__ __forceinline__ float sigf(float x){ return 1.f/(1.f+expf(-x)); }
__device__ __forceinline__ float warp_max(float v){
  #pragma unroll
  for (int o=16;o;o>>=1) v = fmaxf(v, __shfl_xor_sync(0xffffffffu, v, o));
  return v;
}
__device__ __forceinline__ float warp_sum(float v){
  #pragma unroll
  for (int o=16;o;o>>=1) v += __shfl_xor_sync(0xffffffffu, v, o);
  return v;
}

// software grid barrier; NBLK blocks, 1 CTA/SM (co-resident)
__device__ __forceinline__ void gridbar(){
  __syncthreads();
  __threadfence();
  if (threadIdx.x == 0){
    unsigned gen = *((volatile unsigned*)&g_gen);
    if (atomicAdd(&g_cnt, 1u) == NBLK-1u){
      g_cnt = 0u;
      __threadfence();
      atomicExch(&g_gen, gen+1u);
    } else {
      while (*((volatile unsigned*)&g_gen) == gen) { }
      __threadfence();
    }
  }
  __syncthreads();
}

// ---------------- 128x128 fp32 GEMM, 8x8 microtile, double-buffered ----------------
template<bool BT, bool ACC>
__global__ void __launch_bounds__(256) gemm128(
    const float* __restrict__ A, const float* __restrict__ B,
    float* __restrict__ C, const float* __restrict__ bias,
    int M, int Nn, int K, int lda, int ldb, int ldc,
    long sA, long sB, long sC)
{
  A += (long)blockIdx.z * sA; B += (long)blockIdx.z * sB; C += (long)blockIdx.z * sC;
  __shared__ float As[2][8][128];
  __shared__ float Bs[2][8][128];
  const int tid = threadIdx.x;
  const int rBase = blockIdx.y * 128, cBase = blockIdx.x * 128;
  const int tr = tid >> 4, tc = tid & 15;
  const int ar = tid >> 1, akq = (tid & 1) * 4;
  const int garow = rBase + ar;
  const int bk = tid >> 5, bc = (tid & 31) * 4;
  const int gbcol0 = cBase + bc;
  const int gbrow1 = cBase + ar;

  float acc[8][8];
  #pragma unroll
  for (int i=0;i<8;i++)
    #pragma unroll
    for (int j=0;j<8;j++) acc[i][j] = 0.f;

  const int nk = K >> 3;
  float4 pa = make_float4(0.f,0.f,0.f,0.f);
  float4 pb = make_float4(0.f,0.f,0.f,0.f);
  if (garow < M) pa = *(const float4*)(A + (long)garow*lda + akq);
  if (BT){ if (gbrow1 < Nn) pb = *(const float4*)(B + (long)gbrow1*ldb + akq); }
  else   { if (gbcol0 < Nn) pb = *(const float4*)(B + (long)bk*ldb + gbcol0); }
  As[0][akq  ][ar]=pa.x; As[0][akq+1][ar]=pa.y; As[0][akq+2][ar]=pa.z; As[0][akq+3][ar]=pa.w;
  if (BT){ Bs[0][akq][ar]=pb.x; Bs[0][akq+1][ar]=pb.y; Bs[0][akq+2][ar]=pb.z; Bs[0][akq+3][ar]=pb.w; }
  else   { *(float4*)&Bs[0][bk][bc] = pb; }
  __syncthreads();

  for (int kt=0; kt<nk; kt++){
    const int cur = kt & 1;
    if (kt+1 < nk){
      const int ko = (kt+1) << 3;
      pa = make_float4(0.f,0.f,0.f,0.f);
      pb = make_float4(0.f,0.f,0.f,0.f);
      if (garow < M) pa = *(const float4*)(A + (long)garow*lda + ko + akq);
      if (BT){ if (gbrow1 < Nn) pb = *(const float4*)(B + (long)gbrow1*ldb + ko + akq); }
      else   { if (gbcol0 < Nn) pb = *(const float4*)(B + (long)(ko+bk)*ldb + gbcol0); }
    }
    #pragma unroll
    for (int kk=0;kk<8;kk++){
      float4 a0 = *(const float4*)&As[cur][kk][tr*8];
      float4 a1 = *(const float4*)&As[cur][kk][tr*8+4];
      float4 b0 = *(const float4*)&Bs[cur][kk][tc*8];
      float4 b1 = *(const float4*)&Bs[cur][kk][tc*8+4];
      float av[8] = {a0.x,a0.y,a0.z,a0.w,a1.x,a1.y,a1.z,a1.w};
      float bv[8] = {b0.x,b0.y,b0.z,b0.w,b1.x,b1.y,b1.z,b1.w};
      #pragma unroll
      for (int i=0;i<8;i++)
        #pragma unroll
        for (int j=0;j<8;j++) acc[i][j] = fmaf(av[i], bv[j], acc[i][j]);
    }
    if (kt+1 < nk){
      const int nx = (kt+1) & 1;
      As[nx][akq  ][ar]=pa.x; As[nx][akq+1][ar]=pa.y; As[nx][akq+2][ar]=pa.z; As[nx][akq+3][ar]=pa.w;
      if (BT){ Bs[nx][akq][ar]=pb.x; Bs[nx][akq+1][ar]=pb.y; Bs[nx][akq+2][ar]=pb.z; Bs[nx][akq+3][ar]=pb.w; }
      else   { *(float4*)&Bs[nx][bk][bc] = pb; }
    }
    __syncthreads();
  }

  #pragma unroll
  for (int i=0;i<8;i++){
    int row = rBase + tr*8 + i;
    if (row >= M) continue;
    #pragma unroll
    for (int j=0;j<8;j+=4){
      int col = cBase + tc*8 + j;
      if (col >= Nn) continue;
      float4 vv;
      vv.x = acc[i][j]; vv.y = acc[i][j+1]; vv.z = acc[i][j+2]; vv.w = acc[i][j+3];
      if (bias){ vv.x += bias[col]; vv.y += bias[col+1]; vv.z += bias[col+2]; vv.w += bias[col+3]; }
      float* cp = C + (long)row*ldc + col;
      if (ACC){ float4 o = *(const float4*)cp; vv.x+=o.x; vv.y+=o.y; vv.z+=o.z; vv.w+=o.w; }
      *(float4*)cp = vv;
    }
  }
}

// ---------------- generic transpose (R,C) -> (C,R), batched over z ----------------
__global__ void transp(const float* __restrict__ in, float* __restrict__ out,
                       int R, int C, long sIn, long sOut)
{
  in  += (long)blockIdx.z * sIn;
  out += (long)blockIdx.z * sOut;
  __shared__ float t[32][33];
  int c = blockIdx.x*32 + threadIdx.x;
  #pragma unroll
  for (int i=0;i<32;i+=8){
    int r = blockIdx.y*32 + threadIdx.y + i;
    if (r < R && c < C) t[threadIdx.y+i][threadIdx.x] = in[(long)r*C + c];
  }
  __syncthreads();
  int oc = blockIdx.y*32 + threadIdx.x;
  #pragma unroll
  for (int i=0;i<32;i+=8){
    int orow = blockIdx.x*32 + threadIdx.y + i;
    if (orow < C && oc < R) out[(long)orow*R + oc] = t[threadIdx.x][threadIdx.y+i];
  }
}

// ---------------- misc prep kernels ----------------
__global__ void bias_prep(const float* b_ih1, const float* b_hh1,
                          const float* b_ih2, const float* b_hh2){
  int i = blockIdx.x*blockDim.x + threadIdx.x;
  if (i < 4*DH_)  g_b1[i] = b_ih1[i] + b_hh1[i];
  if (i < 4*KEY_) g_b2[i] = b_ih2[i] + b_hh2[i];
}
__global__ void init_state(){
  int i = blockIdx.x*blockDim.x + threadIdx.x;
  if (i < DH_*N_){ g_h1T[i] = 0.f; g_c1T[i] = 0.f; }
  if (i < 512*N_){ g_hc2T[i] = 0.f; }
  if (i < KEY_*N_){ g_c2buf[0][i] = 0.f; g_c2buf[1][i] = 0.f; }
}
__global__ void kb_k(const float* __restrict__ bq){
  int w = threadIdx.x >> 5, lane = threadIdx.x & 31;
  int row = blockIdx.x*8 + w;
  float a = 0.f;
  #pragma unroll
  for (int i=0;i<8;i++) a += g_k[(long)row*256 + lane + i*32] * bq[lane + i*32];
  a = warp_sum(a);
  if (lane == 0) g_kb[row] = a;
}
__global__ void embed_k(const float* __restrict__ E, const int* __restrict__ text){
  int r = blockIdx.x;                 // n*L + l
  int n = r / L_, l = r - n*L_;
  int tok = (l == 0) ? 0 : text[n*L_ + l - 1];
  g_in1[(long)r*IN1LD + threadIdx.x] = E[(long)tok*EMB_ + threadIdx.x];
}
__global__ void softmax1_k(const int* __restrict__ lens){
  __shared__ float red[8];
  int b = blockIdx.x;                 // n*L + l
  int n = b / L_;
  float* row = g_att + (long)b*T_;
  int len = lens[n];
  int t0 = threadIdx.x, t1 = threadIdx.x + 256;
  float e0 = (t0 < len) ? row[t0] : -1e30f;
  float e1 = (t1 < len) ? row[t1] : -1e30f;
  float m = warp_max(fmaxf(e0,e1));
  if ((threadIdx.x & 31) == 0) red[threadIdx.x>>5] = m;
  __syncthreads();
  m = red[0];
  #pragma unroll
  for (int i=1;i<8;i++) m = fmaxf(m, red[i]);
  __syncthreads();
  float p0 = (t0 < len) ? expf(e0 - m) : 0.f;
  float p1 = (t1 < len) ? expf(e1 - m) : 0.f;
  float s = warp_sum(p0 + p1);
  if ((threadIdx.x & 31) == 0) red[threadIdx.x>>5] = s;
  __syncthreads();
  s = red[0];
  #pragma unroll
  for (int i=1;i<8;i++) s += red[i];
  float inv = 1.f / s;
  row[t0] = p0*inv; row[t1] = p1*inv;
}
// gx (n*L+l, 2048) -> gxT (l, col, n)
__global__ void gxT_k(){
  __shared__ float tile[32][33];
  int l = blockIdx.y;
  int colbase = blockIdx.x*32;
  int tx = threadIdx.x, ty = threadIdx.y;
  #pragma unroll
  for (int i=0;i<32;i+=8){
    int n = ty + i;
    tile[n][tx] = g_gx[((long)n*L_ + l)*2048 + colbase + tx];
  }
  __syncthreads();
  #pragma unroll
  for (int i=0;i<32;i+=8){
    int cl = ty + i;
    g_gxT[((long)l*2048 + colbase + cl)*32 + tx] = tile[tx][cl];
  }
}

// ---------------- persistent loop kernel ----------------
// block-level small gemm: out[(colbase+col)*32+n] (+= / =) sum_k W[k][colbase+col]*hT[k][n]
__device__ void blk_gemm16(const float* __restrict__ W, int ldw,
                           const float* __restrict__ hT, int K,
                           int colbase, float* __restrict__ outT,
                           const float* __restrict__ addM,
                           const float* __restrict__ addB,
                           bool accOut, float* sm)
{
  float* Ws = sm;           // [64*16]
  float* hs = sm + 1024;    // [64*32]
  float* ps = sm + 3072;    // [8*512]
  const int t = threadIdx.x;
  const int cg = t & 3;
  const int ng = (t >> 2) & 7;
  const int ks = t >> 5;
  float acc[4][4];
  #pragma unroll
  for (int i=0;i<4;i++)
    #pragma unroll
    for (int j=0;j<4;j++) acc[i][j] = 0.f;

  for (int kt = 0; kt < K; kt += 64){
    {
      int r = t >> 2, c4 = (t & 3) << 2;
      float4 w4 = *(const float4*)(W + (long)(kt + r)*ldw + colbase + c4);
      *(float4*)&Ws[r*16 + c4] = w4;
    }
    {
      const float4* src = (const float4*)(hT + (long)kt*32);
      float4* dst = (float4*)hs;
      dst[t] = src[t];
      dst[t+256] = src[t+256];
    }
    __syncthreads();
    #pragma unroll
    for (int kk=0;kk<8;kk++){
      int k = ks*8 + kk;
      float4 w4 = *(const float4*)&Ws[k*16 + (cg<<2)];
      float4 h4 = *(const float4*)&hs[k*32 + (ng<<2)];
      float w[4] = {w4.x,w4.y,w4.z,w4.w};
      float h[4] = {h4.x,h4.y,h4.z,h4.w};
      #pragma unroll
      for (int i=0;i<4;i++)
        #pragma unroll
        for (int j=0;j<4;j++) acc[i][j] = fmaf(w[i], h[j], acc[i][j]);
    }
    __syncthreads();
  }
  #pragma unroll
  for (int i=0;i<4;i++)
    #pragma unroll
    for (int j=0;j<4;j++)
      ps[ks*512 + ((cg<<2)+i)*32 + (ng<<2)+j] = acc[i][j];
  __syncthreads();
  #pragma unroll
  for (int i=0;i<2;i++){
    int id = t + i*256;
    float s = 0.f;
    #pragma unroll
    for (int k8=0;k8<8;k8++) s += ps[k8*512 + id];
    int col = id >> 5, n = id & 31;
    long o = (long)(colbase + col)*32 + n;
    if (addM) s += addM[o];
    if (addB) s += addB[colbase + col];
    if (accOut) s += outT[o];
    outT[o] = s;
  }
  __syncthreads();
}

// fco variant: K=512 over g_hc2T, W=Wfc (ldw=256), epilogue bias+hardtanh,
// store to g_fco[(n*L+l)*256 + col]
__device__ void blk_gemm16_fco(const float* __restrict__ Wfc,
                               const float* __restrict__ bfc,
                               int l, int colbase, float* sm)
{
  float* Ws = sm;
  float* hs = sm + 1024;
  float* ps = sm + 3072;
  const int t = threadIdx.x;
  const int cg = t & 3;
  const int ng = (t >> 2) & 7;
  const int ks = t >> 5;
  float acc[4][4];
  #pragma unroll
  for (int i=0;i<4;i++)
    #pragma unroll
    for (int j=0;j<4;j++) acc[i][j] = 0.f;

  for (int kt = 0; kt < 512; kt += 64){
    {
      int r = t >> 2, c4 = (t & 3) << 2;
      float4 w4 = *(const float4*)(Wfc + (long)(kt + r)*256 + colbase + c4);
      *(float4*)&Ws[r*16 + c4] = w4;
    }
    {
      const float4* src = (const float4*)(g_hc2T + (long)kt*32);
      float4* dst = (float4*)hs;
      dst[t] = src[t];
      dst[t+256] = src[t+256];
    }
    __syncthreads();
    #pragma unroll
    for (int kk=0;kk<8;kk++){
      int k = ks*8 + kk;
      float4 w4 = *(const float4*)&Ws[k*16 + (cg<<2)];
      float4 h4 = *(const float4*)&hs[k*32 + (ng<<2)];
      float w[4] = {w4.x,w4.y,w4.z,w4.w};
      float h[4] = {h4.x,h4.y,h4.z,h4.w};
      #pragma unroll
      for (int i=0;i<4;i++)
        #pragma unroll
        for (int j=0;j<4;j++) acc[i][j] = fmaf(w[i], h[j], acc[i][j]);
    }
    __syncthreads();
  }
  #pragma unroll
  for (int i=0;i<4;i++)
    #pragma unroll
    for (int j=0;j<4;j++)
      ps[ks*512 + ((cg<<2)+i)*32 + (ng<<2)+j] = acc[i][j];
  __syncthreads();
  #pragma unroll
  for (int i=0;i<2;i++){
    int id = t + i*256;
    float s = 0.f;
    #pragma unroll
    for (int k8=0;k8<8;k8++) s += ps[k8*512 + id];
    int col = id >> 5, n = id & 31;
    s += bfc[colbase + col];
    s = fminf(1.f, fmaxf(-1.f, s));
    g_fco[((long)n*L_ + l)*256 + colbase + col] = s;
  }
  __syncthreads();
}

__global__ void __launch_bounds__(256, 1) loop_k(
    const int* __restrict__ lens,
    const float* __restrict__ Wfc, const float* __restrict__ bfc,
    float* __restrict__ out_att)
{
  __shared__ float sm[8704];
  const int b = blockIdx.x;
  const int t = threadIdx.x;

  for (int l = 0; l < L_; l++){
    const int p = l & 1;
    // ---- S1: g1 = gxT[l] + h1 @ Whh1T  (blocks 0..127) ----
    if (b < 128)
      blk_gemm16(g_Whh1T, 2048, g_h1T, 512, b*16, g_g1T,
                 g_gxT + (long)l*2048*32, nullptr, false, sm);
    gridbar();
    // ---- S2: g2 = b2 + h2_prev @ Whh2T (0..63) ; LSTM1 update (64..127) ----
    if (b < 64){
      blk_gemm16(g_Whh2T, 1024, g_hc2T, 256, b*16, g_g2T,
                 nullptr, g_b2, false, sm);
    } else if (b < 128){
      int id = (b-64)*256 + t;
      int n = id & 31, j = id >> 5;
      float gi = g_g1T[j*32+n];
      float gf = g_g1T[(512+j)*32+n];
      float gg = g_g1T[(1024+j)*32+n];
      float go = g_g1T[(1536+j)*32+n];
      float c = sigf(gf)*g_c1T[j*32+n] + sigf(gi)*tanhf(gg);
      g_c1T[j*32+n] = c;
      g_h1T[j*32+n] = sigf(go)*tanhf(c);
    }
    gridbar();
    // ---- S3: g2 += h1 @ Wih2T (blocks 0..63) ----
    if (b < 64)
      blk_gemm16(g_Wih2T, 1024, g_h1T, 512, b*16, g_g2T,
                 nullptr, nullptr, true, sm);
    gridbar();
    // ---- S45: per (n, t-tile): h2/c2 recompute; energy; tile-local softmax pieces ----
    if (b < 128){
      int n = b >> 2, s = b & 3;
      float* h2s = sm;            // [256]
      float* ep  = sm + 256;      // [256]
      float* pe  = sm + 512;      // [128]
      float* red = sm + 648;      // [1]
      {
        int e = t;
        float gi = g_g2T[e*32+n];
        float gf = g_g2T[(256+e)*32+n];
        float gg = g_g2T[(512+e)*32+n];
        float go = g_g2T[(768+e)*32+n];
        float c = sigf(gf)*g_c2buf[p][e*32+n] + sigf(gi)*tanhf(gg);
        float h = sigf(go)*tanhf(c);
        h2s[e] = h;
        if (s == 0){ g_hc2T[e*32+n] = h; g_c2buf[1-p][e*32+n] = c; }
      }
      __syncthreads();
      {
        int tl = t & 127, half = t >> 7;
        int tg = s*128 + tl;
        const float* kq = g_kqT + ((long)n*256 + half*128)*T_ + tg;
        const float* hh = h2s + half*128;
        float a0=0.f, a1=0.f, a2=0.f, a3=0.f;
        #pragma unroll
        for (int e=0;e<128;e+=4){
          a0 = fmaf(hh[e  ], kq[(long)(e  )*T_], a0);
          a1 = fmaf(hh[e+1], kq[(long)(e+1)*T_], a1);
          a2 = fmaf(hh[e+2], kq[(long)(e+2)*T_], a2);
          a3 = fmaf(hh[e+3], kq[(long)(e+3)*T_], a3);
        }
        ep[half*128 + tl] = (a0+a1)+(a2+a3);
      }
      __syncthreads();
      float eng = -1e30f; bool valid = false;
      if (t < 128){
        int tg = s*128 + t;
        eng = ep[t] + ep[128+t] + g_kb[n*T_ + tg];
        valid = (tg < lens[n]);
        if (!valid) eng = -1e30f;
        pe[t] = eng;
      }
      __syncthreads();
      if (t < 32){
        float m = fmaxf(fmaxf(pe[t],pe[t+32]), fmaxf(pe[t+64],pe[t+96]));
        m = warp_max(m);
        if (t == 0){ red[0] = m; g_emax[n*4 + s] = m; }
      }
      __syncthreads();
      float m_s = red[0];
      if (t < 128){
        float pv = valid ? expf(eng - m_s) : 0.f;
        pe[t] = pv;
        if (n == 0) g_expe0[s*128 + t] = pv;
      }
      __syncthreads();
      if (t < 32){
        float su = pe[t] + pe[t+32] + pe[t+64] + pe[t+96];
        su = warp_sum(su);
        if (t == 0) g_esum[n*4 + s] = su;
      }
      {
        int d = t;
        const float* vv = g_v + ((long)n*T_ + s*128)*256 + d;
        float a0=0.f, a1=0.f, a2=0.f, a3=0.f;
        #pragma unroll
        for (int tt=0;tt<128;tt+=4){
          a0 = fmaf(pe[tt  ], vv[(long)(tt  )*256], a0);
          a1 = fmaf(pe[tt+1], vv[(long)(tt+1)*256], a1);
          a2 = fmaf(pe[tt+2], vv[(long)(tt+2)*256], a2);
          a3 = fmaf(pe[tt+3], vv[(long)(tt+3)*256], a3);
        }
        g_P[((s*32 + n)<<8) + d] = (a0+a1)+(a2+a3);
      }
    }
    gridbar();
    // ---- S5b: combine tiles -> ctx2 rows of g_hc2T (blocks 0..15), attns (block 16) ----
    if (b < 16){
      float* sw = sm;   // [128]: per-(n,s) normalized tile weight
      if (t < 32){
        float m0=g_emax[t*4], m1=g_emax[t*4+1], m2=g_emax[t*4+2], m3=g_emax[t*4+3];
        float M = fmaxf(fmaxf(m0,m1), fmaxf(m2,m3));
        float w0=expf(m0-M), w1=expf(m1-M), w2=expf(m2-M), w3=expf(m3-M);
        float D = g_esum[t*4]*w0 + g_esum[t*4+1]*w1 + g_esum[t*4+2]*w2 + g_esum[t*4+3]*w3;
        float inv = 1.f / D;
        sw[t*4]=w0*inv; sw[t*4+1]=w1*inv; sw[t*4+2]=w2*inv; sw[t*4+3]=w3*inv;
      }
      __syncthreads();
      int n = t & 31, dg = t >> 5;     // 8 d-slots per pass
      #pragma unroll
      for (int i=0;i<2;i++){
        int d = b*16 + i*8 + dg;
        float a = g_P[(n<<8)+d]*sw[n*4]        + g_P[((32+n)<<8)+d]*sw[n*4+1]
                + g_P[((64+n)<<8)+d]*sw[n*4+2] + g_P[((96+n)<<8)+d]*sw[n*4+3];
        g_hc2T[(256+d)*32 + n] = a;
      }
      __syncthreads();
    } else if (b == 16){
      float* sw = sm;   // [4]
      if (t < 4){
        float m0=g_emax[0], m1=g_emax[1], m2=g_emax[2], m3=g_emax[3];
        float M = fmaxf(fmaxf(m0,m1), fmaxf(m2,m3));
        float ms = (t==0)?m0:(t==1)?m1:(t==2)?m2:m3;
        float w0=expf(m0-M), w1=expf(m1-M), w2=expf(m2-M), w3=expf(m3-M);
        float D = g_esum[0]*w0 + g_esum[1]*w1 + g_esum[2]*w2 + g_esum[3]*w3;
        sw[t] = expf(ms - M) / D;
      }
      __syncthreads();
      #pragma unroll
      for (int i=0;i<2;i++){
        int idx = t + i*256;
        out_att[(long)l*T_ + idx] = g_expe0[idx] * sw[idx >> 7];
      }
      __syncthreads();
    }
    gridbar();
    // ---- S6: fco = hardtanh([h2|ctx2] @ Wfc + bfc) (blocks 0..15); no trailing barrier ----
    if (b < 16)
      blk_gemm16_fco(Wfc, bfc, l, b*16, sm);
    // next S1 touches only g1T/gxT/h1T/weights; S6's hc2T rows are rewritten
    // 3-4 barriers later (S45/S5b of step l+1), after S6 blocks passed S1's barrier.
  }
}

// ---------------- launch ----------------
extern "C" void kernel_launch(void* const* d_in, const int* in_sizes, int n_in,
                              void* d_out, int out_size) {
  const float* enc    = (const float*)d_in[0];
  const int*   text   = (const int*)  d_in[1];
  const int*   lens   = (const int*)  d_in[2];
  const float* E      = (const float*)d_in[3];
  const float* Wk     = (const float*)d_in[4];
  const float* bk     = (const float*)d_in[5];
  const float* Wv     = (const float*)d_in[6];
  const float* bv     = (const float*)d_in[7];
  const float* Wq     = (const float*)d_in[8];
  const float* bq     = (const float*)d_in[9];
  const float* W_ih1  = (const float*)d_in[10];
  const float* W_hh1  = (const float*)d_in[11];
  const float* b_ih1  = (const float*)d_in[12];
  const float* b_hh1  = (const float*)d_in[13];
  const float* W_ih2  = (const float*)d_in[14];
  const float* W_hh2  = (const float*)d_in[15];
  const float* b_ih2  = (const float*)d_in[16];
  const float* b_hh2  = (const float*)d_in[17];
  const float* Wfc    = (const float*)d_in[18];
  const float* bfc    = (const float*)d_in[19];
  const float* b_char = (const float*)d_in[20];
  float* out = (float*)d_out;

  float *pWhh1T, *pWih2T, *pWhh2T, *pK, *pV, *pKq, *pKqT, *pIn1, *pQ1, *pAtt, *pGx, *pFco, *pB1;
  cudaGetSymbolAddress((void**)&pWhh1T, g_Whh1T);
  cudaGetSymbolAddress((void**)&pWih2T, g_Wih2T);
  cudaGetSymbolAddress((void**)&pWhh2T, g_Whh2T);
  cudaGetSymbolAddress((void**)&pK,   g_k);
  cudaGetSymbolAddress((void**)&pV,   g_v);
  cudaGetSymbolAddress((void**)&pKq,  g_kq);
  cudaGetSymbolAddress((void**)&pKqT, g_kqT);
  cudaGetSymbolAddress((void**)&pIn1, g_in1);
  cudaGetSymbolAddress((void**)&pQ1,  g_q1);
  cudaGetSymbolAddress((void**)&pAtt, g_att);
  cudaGetSymbolAddress((void**)&pGx,  g_gx);
  cudaGetSymbolAddress((void**)&pFco, g_fco);
  cudaGetSymbolAddress((void**)&pB1,  g_b1);

  bias_prep<<<8, 256>>>(b_ih1, b_hh1, b_ih2, b_hh2);
  init_state<<<64, 256>>>();
  embed_k<<<N_*L_, 256>>>(E, text);

  gemm128<false,false><<<dim3(2,128,1), 256>>>(enc, Wk, pK, bk,
      N_*T_, KEY_, ENC_, ENC_, KEY_, KEY_, 0,0,0);
  gemm128<false,false><<<dim3(2,128,1), 256>>>(enc, Wv, pV, bv,
      N_*T_, KEY_, ENC_, ENC_, KEY_, KEY_, 0,0,0);
  gemm128<true,false><<<dim3(2,128,1), 256>>>(pK, Wq, pKq, nullptr,
      N_*T_, 256, KEY_, KEY_, KEY_, 256, 0,0,0);

  kb_k<<<N_*T_/8, 256>>>(bq);
  transp<<<dim3(16,64,1), dim3(32,8)>>>(W_hh1, pWhh1T, 2048, 512, 0, 0);
  transp<<<dim3(16,32,1), dim3(32,8)>>>(W_ih2, pWih2T, 1024, 512, 0, 0);
  transp<<<dim3(8,32,1),  dim3(32,8)>>>(W_hh2, pWhh2T, 1024, 256, 0, 0);
  transp<<<dim3(8,16,N_), dim3(32,8)>>>(pKq, pKqT, T_, 256, (long)T_*256, (long)256*T_);

  gemm128<false,false><<<dim3(2,50,1), 256>>>(pIn1, Wq, pQ1, bq,
      N_*L_, KEY_, EMB_, IN1LD, KEY_, KEY_, 0,0,0);
  gemm128<true,false><<<dim3(4,2,N_), 256>>>(pQ1, pK, pAtt, nullptr,
      L_, T_, KEY_, KEY_, KEY_, T_, (long)L_*KEY_, (long)T_*KEY_, (long)L_*T_);
  softmax1_k<<<N_*L_, 256>>>(lens);
  gemm128<false,false><<<dim3(2,2,N_), 256>>>(pAtt, pV, pIn1 + 256, nullptr,
      L_, KEY_, T_, T_, KEY_, IN1LD, (long)L_*T_, (long)T_*KEY_, (long)L_*IN1LD);
  gemm128<true,false><<<dim3(16,50,1), 256>>>(pIn1, W_ih1, pGx, pB1,
      N_*L_, 4*DH_, EMB_+KEY_, IN1LD, EMB_+KEY_, 4*DH_, 0,0,0);
  gxT_k<<<dim3(64, L_), dim3(32,8)>>>();

  loop_k<<<NBLK, 256>>>(lens, Wfc, bfc, out + (long)N_*L_*VOC_);

  gemm128<true,false><<<dim3(79,50,1), 256>>>(pFco, E, out, b_char,
      N_*L_, VOC_, EMB_, EMB_, EMB_, VOC_, 0,0,0);
}

// round 17
// speedup vs baseline: 1.8981x; 1.0180x over previous
#include <cuda_runtime.h>
#include <cuda_bf16.h>
#include <math.h>

#define N_   32
#define T_   512
#define L_   200
#define EMB_ 256
#define KEY_ 256
#define DH_  512
#define ENC_ 1024
#define VOC_ 10000
#define NBLK 148
#define IN1LD 512

// ---------------- static device scratch (no allocations) ----------------
__device__ float g_k   [N_*T_*KEY_];
__device__ float g_v   [N_*T_*KEY_];
__device__ float g_kq  [N_*T_*KEY_];
__device__ float g_kqT [N_*KEY_*T_];      // (N,256,T)
__device__ float g_kb  [N_*T_];
__device__ float g_in1 [N_*L_*IN1LD];     // fused [emb | ctx1]
__device__ float g_q1  [N_*L_*KEY_];
__device__ float g_att [N_*L_*T_];
__device__ float g_gx  [N_*L_*4*DH_];
__device__ float g_gxT [L_*4*DH_*N_];     // (l, col2048, n)
__device__ float g_fco [N_*L_*EMB_];
__device__ float g_Whh1T[DH_*4*DH_];      // (512,2048)
__device__ float g_Wih2T[DH_*4*KEY_];     // (512,1024)
__device__ float g_Whh2T[KEY_*4*KEY_];    // (256,1024)
__device__ float g_b1[4*DH_];
__device__ float g_b2[4*KEY_];
__device__ float g_h1buf[2][DH_*N_];      // (j,n) double-buffered
__device__ float g_c1T[DH_*N_];
__device__ float g_h2buf[2][KEY_*N_];     // (e,n) double-buffered
__device__ float g_c2[KEY_*N_];
__device__ float g_h2N[N_*KEY_];          // (n,e) for attention phase
__device__ float g_emax[N_*4], g_esum[N_*4];
__device__ float g_P[4*KEY_*N_];          // (s,e,n) tile-scaled ctx partials
__device__ float g_expe0[T_];
__device__ unsigned g_flag[NBLK];
__device__ unsigned g_gen;

// ---------------- helpers ----------------
__device__ __forceinline__ float sigf(float x){ return 1.f/(1.f+expf(-x)); }
__device__ __forceinline__ float warp_max(float v){
  #pragma unroll
  for (int o=16;o;o>>=1) v = fmaxf(v, __shfl_xor_sync(0xffffffffu, v, o));
  return v;
}
__device__ __forceinline__ float warp_sum(float v){
  #pragma unroll
  for (int o=16;o;o>>=1) v += __shfl_xor_sync(0xffffffffu, v, o);
  return v;
}

// flag-array grid barrier: block b>0 posts g_flag[b]=target; block 0 aggregates
// and publishes g_gen=target. target monotonic within a launch; reset by init_state.
__device__ __forceinline__ void gb(int b, unsigned target){
  __syncthreads();
  __threadfence();
  if (b == 0){
    int t = threadIdx.x;
    if (t >= 1 && t < NBLK){
      while (((volatile unsigned*)g_flag)[t] < target) {}
    }
    __syncthreads();
    if (t == 0){
      __threadfence();
      *((volatile unsigned*)&g_gen) = target;
    }
    __syncthreads();
  } else {
    if (threadIdx.x == 0){
      ((volatile unsigned*)g_flag)[b] = target;
      while (*((volatile unsigned*)&g_gen) < target) {}
      __threadfence();
    }
    __syncthreads();
  }
}

// ---------------- 128x128 fp32 GEMM, 8x8 microtile, double-buffered ----------------
template<bool BT, bool ACC>
__global__ void __launch_bounds__(256) gemm128(
    const float* __restrict__ A, const float* __restrict__ B,
    float* __restrict__ C, const float* __restrict__ bias,
    int M, int Nn, int K, int lda, int ldb, int ldc,
    long sA, long sB, long sC)
{
  A += (long)blockIdx.z * sA; B += (long)blockIdx.z * sB; C += (long)blockIdx.z * sC;
  __shared__ float As[2][8][128];
  __shared__ float Bs[2][8][128];
  const int tid = threadIdx.x;
  const int rBase = blockIdx.y * 128, cBase = blockIdx.x * 128;
  const int tr = tid >> 4, tc = tid & 15;
  const int ar = tid >> 1, akq = (tid & 1) * 4;
  const int garow = rBase + ar;
  const int bk = tid >> 5, bc = (tid & 31) * 4;
  const int gbcol0 = cBase + bc;
  const int gbrow1 = cBase + ar;

  float acc[8][8];
  #pragma unroll
  for (int i=0;i<8;i++)
    #pragma unroll
    for (int j=0;j<8;j++) acc[i][j] = 0.f;

  const int nk = K >> 3;
  float4 pa = make_float4(0.f,0.f,0.f,0.f);
  float4 pb = make_float4(0.f,0.f,0.f,0.f);
  if (garow < M) pa = *(const float4*)(A + (long)garow*lda + akq);
  if (BT){ if (gbrow1 < Nn) pb = *(const float4*)(B + (long)gbrow1*ldb + akq); }
  else   { if (gbcol0 < Nn) pb = *(const float4*)(B + (long)bk*ldb + gbcol0); }
  As[0][akq  ][ar]=pa.x; As[0][akq+1][ar]=pa.y; As[0][akq+2][ar]=pa.z; As[0][akq+3][ar]=pa.w;
  if (BT){ Bs[0][akq][ar]=pb.x; Bs[0][akq+1][ar]=pb.y; Bs[0][akq+2][ar]=pb.z; Bs[0][akq+3][ar]=pb.w; }
  else   { *(float4*)&Bs[0][bk][bc] = pb; }
  __syncthreads();

  for (int kt=0; kt<nk; kt++){
    const int cur = kt & 1;
    if (kt+1 < nk){
      const int ko = (kt+1) << 3;
      pa = make_float4(0.f,0.f,0.f,0.f);
      pb = make_float4(0.f,0.f,0.f,0.f);
      if (garow < M) pa = *(const float4*)(A + (long)garow*lda + ko + akq);
      if (BT){ if (gbrow1 < Nn) pb = *(const float4*)(B + (long)gbrow1*ldb + ko + akq); }
      else   { if (gbcol0 < Nn) pb = *(const float4*)(B + (long)(ko+bk)*ldb + gbcol0); }
    }
    #pragma unroll
    for (int kk=0;kk<8;kk++){
      float4 a0 = *(const float4*)&As[cur][kk][tr*8];
      float4 a1 = *(const float4*)&As[cur][kk][tr*8+4];
      float4 b0 = *(const float4*)&Bs[cur][kk][tc*8];
      float4 b1 = *(const float4*)&Bs[cur][kk][tc*8+4];
      float av[8] = {a0.x,a0.y,a0.z,a0.w,a1.x,a1.y,a1.z,a1.w};
      float bv[8] = {b0.x,b0.y,b0.z,b0.w,b1.x,b1.y,b1.z,b1.w};
      #pragma unroll
      for (int i=0;i<8;i++)
        #pragma unroll
        for (int j=0;j<8;j++) acc[i][j] = fmaf(av[i], bv[j], acc[i][j]);
    }
    if (kt+1 < nk){
      const int nx = (kt+1) & 1;
      As[nx][akq  ][ar]=pa.x; As[nx][akq+1][ar]=pa.y; As[nx][akq+2][ar]=pa.z; As[nx][akq+3][ar]=pa.w;
      if (BT){ Bs[nx][akq][ar]=pb.x; Bs[nx][akq+1][ar]=pb.y; Bs[nx][akq+2][ar]=pb.z; Bs[nx][akq+3][ar]=pb.w; }
      else   { *(float4*)&Bs[nx][bk][bc] = pb; }
    }
    __syncthreads();
  }

  #pragma unroll
  for (int i=0;i<8;i++){
    int row = rBase + tr*8 + i;
    if (row >= M) continue;
    #pragma unroll
    for (int j=0;j<8;j+=4){
      int col = cBase + tc*8 + j;
      if (col >= Nn) continue;
      float4 vv;
      vv.x = acc[i][j]; vv.y = acc[i][j+1]; vv.z = acc[i][j+2]; vv.w = acc[i][j+3];
      if (bias){ vv.x += bias[col]; vv.y += bias[col+1]; vv.z += bias[col+2]; vv.w += bias[col+3]; }
      float* cp = C + (long)row*ldc + col;
      if (ACC){ float4 o = *(const float4*)cp; vv.x+=o.x; vv.y+=o.y; vv.z+=o.z; vv.w+=o.w; }
      *(float4*)cp = vv;
    }
  }
}

// ---------------- transpose ----------------
__global__ void transp(const float* __restrict__ in, float* __restrict__ out,
                       int R, int C, long sIn, long sOut)
{
  in  += (long)blockIdx.z * sIn;
  out += (long)blockIdx.z * sOut;
  __shared__ float t[32][33];
  int c = blockIdx.x*32 + threadIdx.x;
  #pragma unroll
  for (int i=0;i<32;i+=8){
    int r = blockIdx.y*32 + threadIdx.y + i;
    if (r < R && c < C) t[threadIdx.y+i][threadIdx.x] = in[(long)r*C + c];
  }
  __syncthreads();
  int oc = blockIdx.y*32 + threadIdx.x;
  #pragma unroll
  for (int i=0;i<32;i+=8){
    int orow = blockIdx.x*32 + threadIdx.y + i;
    if (orow < C && oc < R) out[(long)orow*R + oc] = t[threadIdx.x][threadIdx.y+i];
  }
}

// ---------------- prep kernels ----------------
__global__ void bias_prep(const float* b_ih1, const float* b_hh1,
                          const float* b_ih2, const float* b_hh2){
  int i = blockIdx.x*blockDim.x + threadIdx.x;
  if (i < 4*DH_)  g_b1[i] = b_ih1[i] + b_hh1[i];
  if (i < 4*KEY_) g_b2[i] = b_ih2[i] + b_hh2[i];
}
__global__ void init_state(){
  int i = blockIdx.x*blockDim.x + threadIdx.x;  // 64*256 = 16384
  if (i < DH_*N_){ g_h1buf[0][i]=0.f; g_h1buf[1][i]=0.f; g_c1T[i]=0.f; }
  if (i < KEY_*N_){ g_h2buf[0][i]=0.f; g_h2buf[1][i]=0.f; g_c2[i]=0.f; }
  if (i < NBLK) g_flag[i] = 0u;
  if (i == 0) g_gen = 0u;
}
__global__ void kb_k(const float* __restrict__ bq){
  int w = threadIdx.x >> 5, lane = threadIdx.x & 31;
  int row = blockIdx.x*8 + w;
  float a = 0.f;
  #pragma unroll
  for (int i=0;i<8;i++) a += g_k[(long)row*256 + lane + i*32] * bq[lane + i*32];
  a = warp_sum(a);
  if (lane == 0) g_kb[row] = a;
}
__global__ void embed_k(const float* __restrict__ E, const int* __restrict__ text){
  int r = blockIdx.x;
  int n = r / L_, l = r - n*L_;
  int tok = (l == 0) ? 0 : text[n*L_ + l - 1];
  g_in1[(long)r*IN1LD + threadIdx.x] = E[(long)tok*EMB_ + threadIdx.x];
}
__global__ void softmax1_k(const int* __restrict__ lens){
  __shared__ float red[8];
  int b = blockIdx.x;
  int n = b / L_;
  float* row = g_att + (long)b*T_;
  int len = lens[n];
  int t0 = threadIdx.x, t1 = threadIdx.x + 256;
  float e0 = (t0 < len) ? row[t0] : -1e30f;
  float e1 = (t1 < len) ? row[t1] : -1e30f;
  float m = warp_max(fmaxf(e0,e1));
  if ((threadIdx.x & 31) == 0) red[threadIdx.x>>5] = m;
  __syncthreads();
  m = red[0];
  #pragma unroll
  for (int i=1;i<8;i++) m = fmaxf(m, red[i]);
  __syncthreads();
  float p0 = (t0 < len) ? expf(e0 - m) : 0.f;
  float p1 = (t1 < len) ? expf(e1 - m) : 0.f;
  float s = warp_sum(p0 + p1);
  if ((threadIdx.x & 31) == 0) red[threadIdx.x>>5] = s;
  __syncthreads();
  s = red[0];
  #pragma unroll
  for (int i=1;i<8;i++) s += red[i];
  float inv = 1.f / s;
  row[t0] = p0*inv; row[t1] = p1*inv;
}
__global__ void gxT_k(){
  __shared__ float tile[32][33];
  int l = blockIdx.y;
  int colbase = blockIdx.x*32;
  int tx = threadIdx.x, ty = threadIdx.y;
  #pragma unroll
  for (int i=0;i<32;i+=8){
    int n = ty + i;
    tile[n][tx] = g_gx[((long)n*L_ + l)*2048 + colbase + tx];
  }
  __syncthreads();
  #pragma unroll
  for (int i=0;i<32;i+=8){
    int cl = ty + i;
    g_gxT[((long)l*2048 + colbase + cl)*32 + tx] = tile[tx][cl];
  }
}

// ---------------- loop phase device functions ----------------
// shared layout (floats): Ws[0..1024) hs[1024..3072) ps[3072..7168)
// fco extra: ctx2s[3072..11264) (aliases ps; disjoint lifetimes) sw[11264..11392)

#define GEMM_TILE_BODY(Wsrc, ldw, colb, hsrc) { \
  int r_ = t >> 2; \
  float4 w4_ = *(const float4*)((Wsrc) + (long)(kt + r_)*(ldw) + (colb)); \
  *(float4*)&Ws[r_*16 + (cg<<2)] = w4_; \
  const float4* src_ = (const float4*)((hsrc) + (long)kt*32); \
  float4* dst_ = (float4*)hs; \
  dst_[t] = src_[t]; dst_[t+256] = src_[t+256]; \
  __syncthreads(); \
  _Pragma("unroll") \
  for (int kk=0;kk<8;kk++){ \
    int k_ = ks*8 + kk; \
    float4 wr_ = *(const float4*)&Ws[k_*16 + (cg<<2)]; \
    float4 hr_ = *(const float4*)&hs[k_*32 + (ng<<2)]; \
    float wv_[4] = {wr_.x,wr_.y,wr_.z,wr_.w}; \
    float hv_[4] = {hr_.x,hr_.y,hr_.z,hr_.w}; \
    _Pragma("unroll") for (int i_=0;i_<4;i_++) \
      _Pragma("unroll") for (int j_=0;j_<4;j_++) \
        acc[i_][j_] = fmaf(wv_[i_], hv_[j_], acc[i_][j_]); \
  } \
  __syncthreads(); }

// P1: g1 = gxT[l] + h1_prev @ Whh1T (gate-grouped cols), fused LSTM1 update.
__device__ void p1_fused(int b, int l, int p, float* sm){
  float* Ws = sm; float* hs = sm + 1024; float* ps = sm + 3072;
  const int t = threadIdx.x;
  const int cg = t & 3, ng = (t >> 2) & 7, ks = t >> 5;
  const float* h1rd = g_h1buf[p];
  float acc[4][4];
  #pragma unroll
  for (int i=0;i<4;i++)
    #pragma unroll
    for (int j=0;j<4;j++) acc[i][j] = 0.f;

  for (int kt = 0; kt < 512; kt += 64)
    GEMM_TILE_BODY(g_Whh1T, 2048, cg*512 + b*4, h1rd)

  #pragma unroll
  for (int i=0;i<4;i++)
    #pragma unroll
    for (int j=0;j<4;j++)
      ps[ks*512 + ((cg<<2)+i)*32 + (ng<<2)+j] = acc[i][j];
  __syncthreads();

  if (t < 128){
    int jj = t >> 5, n = t & 31, j = b*4 + jj;
    float sg[4];
    #pragma unroll
    for (int g=0; g<4; g++){
      float s = 0.f;
      #pragma unroll
      for (int k8=0;k8<8;k8++) s += ps[k8*512 + (g*4+jj)*32 + n];
      s += g_gxT[((long)l*2048 + g*512 + j)*32 + n];
      sg[g] = s;
    }
    float c = sigf(sg[1])*g_c1T[j*32+n] + sigf(sg[0])*tanhf(sg[2]);
    g_c1T[j*32+n] = c;
    g_h1buf[1-p][j*32+n] = sigf(sg[3])*tanhf(c);
  }
}

// P2: g2 = b2 + h2_prev @ Whh2T + h1 @ Wih2T (gate-grouped), fused LSTM2 update.
__device__ void p2_fused(int b, int p, float* sm){
  float* Ws = sm; float* hs = sm + 1024; float* ps = sm + 3072;
  const int t = threadIdx.x;
  const int cg = t & 3, ng = (t >> 2) & 7, ks = t >> 5;
  const float* h2rd = g_h2buf[p];
  const float* h1rd = g_h1buf[1-p];   // h1 of current step (written by P1)
  float acc[4][4];
  #pragma unroll
  for (int i=0;i<4;i++)
    #pragma unroll
    for (int j=0;j<4;j++) acc[i][j] = 0.f;

  for (int kt = 0; kt < 256; kt += 64)
    GEMM_TILE_BODY(g_Whh2T, 1024, cg*256 + b*4, h2rd)
  for (int kt = 0; kt < 512; kt += 64)
    GEMM_TILE_BODY(g_Wih2T, 1024, cg*256 + b*4, h1rd)

  #pragma unroll
  for (int i=0;i<4;i++)
    #pragma unroll
    for (int j=0;j<4;j++)
      ps[ks*512 + ((cg<<2)+i)*32 + (ng<<2)+j] = acc[i][j];
  __syncthreads();

  if (t < 128){
    int jj = t >> 5, n = t & 31, e = b*4 + jj;
    float sg[4];
    #pragma unroll
    for (int g=0; g<4; g++){
      float s = g_b2[g*256 + e];
      #pragma unroll
      for (int k8=0;k8<8;k8++) s += ps[k8*512 + (g*4+jj)*32 + n];
      sg[g] = s;
    }
    float c = sigf(sg[1])*g_c2[e*32+n] + sigf(sg[0])*tanhf(sg[2]);
    g_c2[e*32+n] = c;
    float h = sigf(sg[3])*tanhf(c);
    g_h2buf[1-p][e*32+n] = h;
    g_h2N[n*256 + e] = h;
  }
}

// P3: per (n, t-tile): energy, tile-local softmax pieces, partial ctx -> g_P (s,e,n).
__device__ void p3_attn(int b, const int* __restrict__ lens, float* sm){
  const int t = threadIdx.x;
  int n = b >> 2, s = b & 3;
  float* h2s = sm;          // [256]
  float* ep  = sm + 256;    // [256]
  float* pe  = sm + 512;    // [128]
  float* red = sm + 648;    // [1]

  h2s[t] = g_h2N[n*256 + t];
  __syncthreads();
  {
    int tl = t & 127, half = t >> 7;
    const float* kq = g_kqT + ((long)n*256 + half*128)*T_ + s*128 + tl;
    const float* hh = h2s + half*128;
    float a0=0.f, a1=0.f, a2=0.f, a3=0.f;
    #pragma unroll
    for (int e=0;e<128;e+=4){
      a0 = fmaf(hh[e  ], kq[(long)(e  )*T_], a0);
      a1 = fmaf(hh[e+1], kq[(long)(e+1)*T_], a1);
      a2 = fmaf(hh[e+2], kq[(long)(e+2)*T_], a2);
      a3 = fmaf(hh[e+3], kq[(long)(e+3)*T_], a3);
    }
    ep[half*128 + tl] = (a0+a1)+(a2+a3);
  }
  __syncthreads();
  float eng = -1e30f; bool valid = false;
  if (t < 128){
    int tg = s*128 + t;
    eng = ep[t] + ep[128+t] + g_kb[n*T_ + tg];
    valid = (tg < lens[n]);
    if (!valid) eng = -1e30f;
    pe[t] = eng;
  }
  __syncthreads();
  if (t < 32){
    float m = fmaxf(fmaxf(pe[t],pe[t+32]), fmaxf(pe[t+64],pe[t+96]));
    m = warp_max(m);
    if (t == 0){ red[0] = m; g_emax[n*4 + s] = m; }
  }
  __syncthreads();
  float m_s = red[0];
  if (t < 128){
    float pv = valid ? expf(eng - m_s) : 0.f;
    pe[t] = pv;
    if (n == 0) g_expe0[s*128 + t] = pv;
  }
  __syncthreads();
  if (t < 32){
    float su = pe[t] + pe[t+32] + pe[t+64] + pe[t+96];
    su = warp_sum(su);
    if (t == 0) g_esum[n*4 + s] = su;
  }
  {
    int d = t;
    const float* vv = g_v + ((long)n*T_ + s*128)*256 + d;
    float a0=0.f, a1=0.f, a2=0.f, a3=0.f;
    #pragma unroll
    for (int tt=0;tt<128;tt+=4){
      a0 = fmaf(pe[tt  ], vv[(long)(tt  )*256], a0);
      a1 = fmaf(pe[tt+1], vv[(long)(tt+1)*256], a1);
      a2 = fmaf(pe[tt+2], vv[(long)(tt+2)*256], a2);
      a3 = fmaf(pe[tt+3], vv[(long)(tt+3)*256], a3);
    }
    g_P[(s*256 + d)*32 + n] = (a0+a1)+(a2+a3);
  }
}

// P5: blocks 0..15 — combine tiles -> ctx2 in smem, then fco gemm (K=512 over [h2|ctx2]).
__device__ void p5_fco(int b, int l, int p,
                       const float* __restrict__ Wfc, const float* __restrict__ bfc,
                       float* sm){
  float* Ws    = sm;
  float* hs    = sm + 1024;
  float* ps    = sm + 3072;   // aliases ctx2s lower half; written only after all tiles
  float* ctx2s = sm + 3072;   // [256*32] (e,n)
  float* sw    = sm + 11264;  // [128]
  const int t = threadIdx.x;
  const int cg = t & 3, ng = (t >> 2) & 7, ks = t >> 5;
  const float* h2cur = g_h2buf[1-p];

  if (t < 32){
    float m0=g_emax[t*4], m1=g_emax[t*4+1], m2=g_emax[t*4+2], m3=g_emax[t*4+3];
    float M = fmaxf(fmaxf(m0,m1), fmaxf(m2,m3));
    float w0=expf(m0-M), w1=expf(m1-M), w2=expf(m2-M), w3=expf(m3-M);
    float D = g_esum[t*4]*w0 + g_esum[t*4+1]*w1 + g_esum[t*4+2]*w2 + g_esum[t*4+3]*w3;
    float inv = 1.f / D;
    sw[t*4]=w0*inv; sw[t*4+1]=w1*inv; sw[t*4+2]=w2*inv; sw[t*4+3]=w3*inv;
  }
  __syncthreads();
  {
    int n = t & 31, eg = t >> 5;
    float w0=sw[n*4], w1=sw[n*4+1], w2=sw[n*4+2], w3=sw[n*4+3];
    #pragma unroll 4
    for (int j=0;j<32;j++){
      int e = eg*32 + j;
      float v = g_P[(e)*32+n]*w0 + g_P[(256+e)*32+n]*w1
              + g_P[(512+e)*32+n]*w2 + g_P[(768+e)*32+n]*w3;
      ctx2s[e*32 + n] = v;
    }
  }
  __syncthreads();

  float acc[4][4];
  #pragma unroll
  for (int i=0;i<4;i++)
    #pragma unroll
    for (int j=0;j<4;j++) acc[i][j] = 0.f;

  for (int kt = 0; kt < 512; kt += 64){
    int r_ = t >> 2;
    float4 w4_ = *(const float4*)(Wfc + (long)(kt + r_)*256 + b*16 + (cg<<2));
    *(float4*)&Ws[r_*16 + (cg<<2)] = w4_;
    const float4* src_ = (kt < 256)
        ? (const float4*)(h2cur + (long)kt*32)
        : (const float4*)(ctx2s + (long)(kt-256)*32);
    float4* dst_ = (float4*)hs;
    dst_[t] = src_[t]; dst_[t+256] = src_[t+256];
    __syncthreads();
    #pragma unroll
    for (int kk=0;kk<8;kk++){
      int k_ = ks*8 + kk;
      float4 wr_ = *(const float4*)&Ws[k_*16 + (cg<<2)];
      float4 hr_ = *(const float4*)&hs[k_*32 + (ng<<2)];
      float wv_[4] = {wr_.x,wr_.y,wr_.z,wr_.w};
      float hv_[4] = {hr_.x,hr_.y,hr_.z,hr_.w};
      #pragma unroll
      for (int i_=0;i_<4;i_++)
        #pragma unroll
        for (int j_=0;j_<4;j_++) acc[i_][j_] = fmaf(wv_[i_], hv_[j_], acc[i_][j_]);
    }
    __syncthreads();
  }
  #pragma unroll
  for (int i=0;i<4;i++)
    #pragma unroll
    for (int j=0;j<4;j++)
      ps[ks*512 + ((cg<<2)+i)*32 + (ng<<2)+j] = acc[i][j];
  __syncthreads();
  #pragma unroll
  for (int i=0;i<2;i++){
    int id = t + i*256;
    float s = 0.f;
    #pragma unroll
    for (int k8=0;k8<8;k8++) s += ps[k8*512 + id];
    int col = id >> 5, n = id & 31;
    s += bfc[b*16 + col];
    s = fminf(1.f, fmaxf(-1.f, s));
    g_fco[((long)n*L_ + l)*256 + b*16 + col] = s;
  }
  __syncthreads();
}

__global__ void __launch_bounds__(256, 1) loop_k(
    const int* __restrict__ lens,
    const float* __restrict__ Wfc, const float* __restrict__ bfc,
    float* __restrict__ out_att)
{
  __shared__ float sm[11392];   // 45.5 KB
  const int b = blockIdx.x;
  const int t = threadIdx.x;
  unsigned bt = 0;

  for (int l = 0; l < L_; l++){
    const int p = l & 1;
    if (b < 128) p1_fused(b, l, p, sm);
    gb(b, ++bt);
    if (b < 64) p2_fused(b, p, sm);
    gb(b, ++bt);
    if (b < 128) p3_attn(b, lens, sm);
    gb(b, ++bt);
    if (b < 16){
      p5_fco(b, l, p, Wfc, bfc, sm);
    } else if (b == 16){
      float* sw = sm;
      if (t < 4){
        float m0=g_emax[0], m1=g_emax[1], m2=g_emax[2], m3=g_emax[3];
        float M = fmaxf(fmaxf(m0,m1), fmaxf(m2,m3));
        float ms = (t==0)?m0:(t==1)?m1:(t==2)?m2:m3;
        float w0=expf(m0-M), w1=expf(m1-M), w2=expf(m2-M), w3=expf(m3-M);
        float D = g_esum[0]*w0 + g_esum[1]*w1 + g_esum[2]*w2 + g_esum[3]*w3;
        sw[t] = expf(ms - M) / D;
      }
      __syncthreads();
      #pragma unroll
      for (int i=0;i<2;i++){
        int idx = t + i*256;
        out_att[(long)l*T_ + idx] = g_expe0[idx] * sw[idx >> 7];
      }
      __syncthreads();
    }
    // no barrier: fco blocks run concurrently with next-step P1; they reach
    // P1's barrier only after finishing fco, and P2/P3 writers of fco's
    // inputs are >=1 barrier beyond that.
  }
}

// ---------------- launch ----------------
extern "C" void kernel_launch(void* const* d_in, const int* in_sizes, int n_in,
                              void* d_out, int out_size) {
  const float* enc    = (const float*)d_in[0];
  const int*   text   = (const int*)  d_in[1];
  const int*   lens   = (const int*)  d_in[2];
  const float* E      = (const float*)d_in[3];
  const float* Wk     = (const float*)d_in[4];
  const float* bk     = (const float*)d_in[5];
  const float* Wv     = (const float*)d_in[6];
  const float* bv     = (const float*)d_in[7];
  const float* Wq     = (const float*)d_in[8];
  const float* bq     = (const float*)d_in[9];
  const float* W_ih1  = (const float*)d_in[10];
  const float* W_hh1  = (const float*)d_in[11];
  const float* b_ih1  = (const float*)d_in[12];
  const float* b_hh1  = (const float*)d_in[13];
  const float* W_ih2  = (const float*)d_in[14];
  const float* W_hh2  = (const float*)d_in[15];
  const float* b_ih2  = (const float*)d_in[16];
  const float* b_hh2  = (const float*)d_in[17];
  const float* Wfc    = (const float*)d_in[18];
  const float* bfc    = (const float*)d_in[19];
  const float* b_char = (const float*)d_in[20];
  float* out = (float*)d_out;

  float *pWhh1T, *pWih2T, *pWhh2T, *pK, *pV, *pKq, *pKqT, *pIn1, *pQ1, *pAtt, *pGx, *pFco, *pB1;
  cudaGetSymbolAddress((void**)&pWhh1T, g_Whh1T);
  cudaGetSymbolAddress((void**)&pWih2T, g_Wih2T);
  cudaGetSymbolAddress((void**)&pWhh2T, g_Whh2T);
  cudaGetSymbolAddress((void**)&pK,   g_k);
  cudaGetSymbolAddress((void**)&pV,   g_v);
  cudaGetSymbolAddress((void**)&pKq,  g_kq);
  cudaGetSymbolAddress((void**)&pKqT, g_kqT);
  cudaGetSymbolAddress((void**)&pIn1, g_in1);
  cudaGetSymbolAddress((void**)&pQ1,  g_q1);
  cudaGetSymbolAddress((void**)&pAtt, g_att);
  cudaGetSymbolAddress((void**)&pGx,  g_gx);
  cudaGetSymbolAddress((void**)&pFco, g_fco);
  cudaGetSymbolAddress((void**)&pB1,  g_b1);

  bias_prep<<<8, 256>>>(b_ih1, b_hh1, b_ih2, b_hh2);
  init_state<<<64, 256>>>();
  embed_k<<<N_*L_, 256>>>(E, text);

  gemm128<false,false><<<dim3(2,128,1), 256>>>(enc, Wk, pK, bk,
      N_*T_, KEY_, ENC_, ENC_, KEY_, KEY_, 0,0,0);
  gemm128<false,false><<<dim3(2,128,1), 256>>>(enc, Wv, pV, bv,
      N_*T_, KEY_, ENC_, ENC_, KEY_, KEY_, 0,0,0);
  gemm128<true,false><<<dim3(2,128,1), 256>>>(pK, Wq, pKq, nullptr,
      N_*T_, 256, KEY_, KEY_, KEY_, 256, 0,0,0);

  kb_k<<<N_*T_/8, 256>>>(bq);
  transp<<<dim3(16,64,1), dim3(32,8)>>>(W_hh1, pWhh1T, 2048, 512, 0, 0);
  transp<<<dim3(16,32,1), dim3(32,8)>>>(W_ih2, pWih2T, 1024, 512, 0, 0);
  transp<<<dim3(8,32,1),  dim3(32,8)>>>(W_hh2, pWhh2T, 1024, 256, 0, 0);
  transp<<<dim3(8,16,N_), dim3(32,8)>>>(pKq, pKqT, T_, 256, (long)T_*256, (long)256*T_);

  gemm128<false,false><<<dim3(2,50,1), 256>>>(pIn1, Wq, pQ1, bq,
      N_*L_, KEY_, EMB_, IN1LD, KEY_, KEY_, 0,0,0);
  gemm128<true,false><<<dim3(4,2,N_), 256>>>(pQ1, pK, pAtt, nullptr,
      L_, T_, KEY_, KEY_, KEY_, T_, (long)L_*KEY_, (long)T_*KEY_, (long)L_*T_);
  softmax1_k<<<N_*L_, 256>>>(lens);
  gemm128<false,false><<<dim3(2,2,N_), 256>>>(pAtt, pV, pIn1 + 256, nullptr,
      L_, KEY_, T_, T_, KEY_, IN1LD, (long)L_*T_, (long)T_*KEY_, (long)L_*IN1LD);
  gemm128<true,false><<<dim3(16,50,1), 256>>>(pIn1, W_ih1, pGx, pB1,
      N_*L_, 4*DH_, EMB_+KEY_, IN1LD, EMB_+KEY_, 4*DH_, 0,0,0);
  gxT_k<<<dim3(64, L_), dim3(32,8)>>>();

  loop_k<<<NBLK, 256>>>(lens, Wfc, bfc, out + (long)N_*L_*VOC_);

  gemm128<true,false><<<dim3(79,50,1), 256>>>(pFco, E, out, b_char,
      N_*L_, VOC_, EMB_, EMB_, EMB_, VOC_, 0,0,0);
}